// round 1
// baseline (speedup 1.0000x reference)
#include <cuda_runtime.h>
#include <math.h>

#define BATCH   4
#define LSEQ    2048
#define ROWS    (BATCH*LSEQ)      // 8192
#define DMODEL  768
#define DINNER  1536
#define NHEADS  24
#define HEADDIM 64
#define DSTATE  128
#define CONVDIM 1792
#define DPROJ   3352              // 2*DINNER + 2*DSTATE + NHEADS

// -------- scratch (device globals; no allocation allowed) --------
__device__ float g_zxbcdt[(size_t)ROWS * DPROJ];   // in_proj output
__device__ float g_xBC[(size_t)ROWS * CONVDIM];    // conv+silu output
__device__ float g_dt[ROWS * NHEADS];
__device__ float g_dA[ROWS * NHEADS];
__device__ float g_y[(size_t)ROWS * DINNER];       // scan output -> gated/normed

// =================================================================
// GEMM (NT): C[M,N] = A[M,K] * B[N,K]^T, optional sigmoid(gate)*C
// BM=128, BN=64, BK=16, 256 threads, 8x4 per-thread tile
// =================================================================
__global__ __launch_bounds__(256) void gemm_nt(
    const float* __restrict__ A, const float* __restrict__ B,
    float* __restrict__ C, int M, int N, int K,
    const float* __restrict__ gate)
{
    __shared__ float As[16][132];
    __shared__ float Bs[16][68];
    const int tid = threadIdx.x;
    const int m0 = blockIdx.y * 128;
    const int n0 = blockIdx.x * 64;
    const int tx = tid & 15;       // n direction (16)
    const int ty = tid >> 4;       // m direction (16)
    const int arow = tid >> 1;           // 0..127
    const int acol = (tid & 1) * 8;      // 0 or 8
    const int brow = tid >> 2;           // 0..63
    const int bcol = (tid & 3) * 4;      // 0,4,8,12
    const bool bval = (n0 + brow) < N;

    const float* Ag = A + (size_t)(m0 + arow) * K + acol;
    const float* Bg = B + (size_t)(n0 + brow) * K + bcol;

    float acc[8][4];
    #pragma unroll
    for (int i = 0; i < 8; i++)
        #pragma unroll
        for (int j = 0; j < 4; j++) acc[i][j] = 0.f;

    for (int k0 = 0; k0 < K; k0 += 16) {
        float4 a0 = *(const float4*)(Ag + k0);
        float4 a1 = *(const float4*)(Ag + k0 + 4);
        float4 bv = bval ? *(const float4*)(Bg + k0) : make_float4(0.f,0.f,0.f,0.f);
        __syncthreads();
        As[acol+0][arow] = a0.x; As[acol+1][arow] = a0.y;
        As[acol+2][arow] = a0.z; As[acol+3][arow] = a0.w;
        As[acol+4][arow] = a1.x; As[acol+5][arow] = a1.y;
        As[acol+6][arow] = a1.z; As[acol+7][arow] = a1.w;
        Bs[bcol+0][brow] = bv.x; Bs[bcol+1][brow] = bv.y;
        Bs[bcol+2][brow] = bv.z; Bs[bcol+3][brow] = bv.w;
        __syncthreads();
        #pragma unroll
        for (int k = 0; k < 16; k++) {
            float a[8], b[4];
            #pragma unroll
            for (int i = 0; i < 8; i++) a[i] = As[k][ty*8 + i];
            #pragma unroll
            for (int j = 0; j < 4; j++) b[j] = Bs[k][tx*4 + j];
            #pragma unroll
            for (int i = 0; i < 8; i++)
                #pragma unroll
                for (int j = 0; j < 4; j++)
                    acc[i][j] = fmaf(a[i], b[j], acc[i][j]);
        }
    }

    float scale = 1.f;
    if (gate) { float g = *gate; scale = 1.f / (1.f + expf(-g)); }
    #pragma unroll
    for (int i = 0; i < 8; i++) {
        const size_t mrow = (size_t)(m0 + ty*8 + i) * N;
        #pragma unroll
        for (int j = 0; j < 4; j++) {
            int n = n0 + tx*4 + j;
            if (n < N) C[mrow + n] = acc[i][j] * scale;
        }
    }
}

// =================================================================
// Causal depthwise conv1d (width 4) + bias + SiLU on xBC slice
// =================================================================
__global__ __launch_bounds__(256) void conv_silu_kernel(
    const float* __restrict__ conv_w, const float* __restrict__ conv_b)
{
    const long idx = (long)blockIdx.x * 256 + threadIdx.x;  // < ROWS*CONVDIM
    const int  c   = (int)(idx % CONVDIM);
    const long row = idx / CONVDIM;
    const int  l   = (int)(row % LSEQ);

    float acc = conv_b[c];
    const float w0 = conv_w[c*4+0], w1 = conv_w[c*4+1];
    const float w2 = conv_w[c*4+2], w3 = conv_w[c*4+3];
    const float* base = g_zxbcdt + (size_t)row * DPROJ + DINNER + c;
    if (l >= 3) acc = fmaf(base[-3*DPROJ], w0, acc);
    if (l >= 2) acc = fmaf(base[-2*DPROJ], w1, acc);
    if (l >= 1) acc = fmaf(base[-1*DPROJ], w2, acc);
    acc = fmaf(base[0], w3, acc);
    g_xBC[idx] = acc / (1.f + expf(-acc));  // silu
}

// =================================================================
// dt = softplus(dt_raw + dt_bias), dA = exp(dt * -exp(A_log))
// =================================================================
__global__ __launch_bounds__(256) void dt_kernel(
    const float* __restrict__ dt_bias, const float* __restrict__ A_log)
{
    const int idx = blockIdx.x * 256 + threadIdx.x;  // < ROWS*NHEADS
    const int h   = idx % NHEADS;
    const int row = idx / NHEADS;
    float v  = g_zxbcdt[(size_t)row * DPROJ + (DINNER + CONVDIM) + h] + dt_bias[h];
    float sp = (v > 20.f) ? v : log1pf(expf(v));
    g_dt[idx] = sp;
    g_dA[idx] = expf(-expf(A_log[h]) * sp);
}

// =================================================================
// Sequential SSM scan: one block per (b, h). 256 threads.
// thread t: p = t>>2 (0..63 head rows), j = t&3 (n chunk of 32).
// 32 state registers per thread. Double-buffered smem + reg prefetch.
// =================================================================
__global__ __launch_bounds__(256) void scan_kernel(const float* __restrict__ Dvec)
{
    const int bh = blockIdx.x;
    const int b  = bh / NHEADS, h = bh % NHEADS;
    const int tid = threadIdx.x;
    const int p = tid >> 2, j = tid & 3;

    __shared__ float sh[2][320];   // [0..63]=x(head), [64..191]=B, [192..319]=C
    float hreg[32];
    #pragma unroll
    for (int k = 0; k < 32; k++) hreg[k] = 0.f;

    const float Dh = Dvec[h];
    const size_t rowbase = (size_t)b * LSEQ;
    // column map: i<64 -> x cols h*64+i ; i in [64,320) -> cols 1472+i (B then C, contiguous)
    const int c0 = (tid < 64) ? (h*HEADDIM + tid) : (1472 + tid);
    const int c1 = 1472 + tid + 256;  // used only by tid<64 -> cols 1728..1791

    { // preload t=0
        const float* r = g_xBC + rowbase * CONVDIM;
        sh[0][tid] = r[c0];
        if (tid < 64) sh[0][tid+256] = r[c1];
    }

    for (int t = 0; t < LSEQ; t++) {
        float r0 = 0.f, r1 = 0.f;
        if (t + 1 < LSEQ) {
            const float* r = g_xBC + (rowbase + t + 1) * CONVDIM;
            r0 = r[c0];
            if (tid < 64) r1 = r[c1];
        }
        const float dtv = g_dt[(rowbase + t)*NHEADS + h];
        const float dAv = g_dA[(rowbase + t)*NHEADS + h];
        __syncthreads();                 // current buffer fully written

        const float* s   = sh[t & 1];
        const float  xp  = s[p];
        const float  coef = dtv * xp;
        const float* Bsh = s + 64  + j*32;
        const float* Csh = s + 192 + j*32;
        float acc = 0.f;
        #pragma unroll
        for (int k = 0; k < 32; k++) {
            hreg[k] = fmaf(hreg[k], dAv, coef * Bsh[k]);
            acc     = fmaf(hreg[k], Csh[k], acc);
        }
        acc += __shfl_down_sync(0xffffffffu, acc, 2);
        acc += __shfl_down_sync(0xffffffffu, acc, 1);
        if (j == 0)
            g_y[(rowbase + t)*DINNER + h*HEADDIM + p] = acc + Dh * xp;

        if (t + 1 < LSEQ) {              // write prefetch into other buffer
            float* sn = sh[(t+1) & 1];
            sn[tid] = r0;
            if (tid < 64) sn[tid+256] = r1;
        }
    }
}

// =================================================================
// y = y * silu(z); y = y * rsqrt(mean(y^2)+eps) * norm_w   (in place)
// one block per row, 256 threads x 6 elements
// =================================================================
__global__ __launch_bounds__(256) void gate_norm_kernel(const float* __restrict__ norm_w)
{
    const int row = blockIdx.x;
    const int tid = threadIdx.x;
    const float* zrow = g_zxbcdt + (size_t)row * DPROJ;   // z = cols [0,1536)
    float* yrow = g_y + (size_t)row * DINNER;

    float v[6];
    float ss = 0.f;
    #pragma unroll
    for (int i = 0; i < 6; i++) {
        int c = tid + i*256;
        float z  = zrow[c];
        float yg = yrow[c] * (z / (1.f + expf(-z)));
        v[i] = yg;
        ss += yg * yg;
    }
    #pragma unroll
    for (int o = 16; o > 0; o >>= 1) ss += __shfl_xor_sync(0xffffffffu, ss, o);
    __shared__ float red[8];
    if ((tid & 31) == 0) red[tid >> 5] = ss;
    __syncthreads();
    if (tid < 32) {
        float s2 = (tid < 8) ? red[tid] : 0.f;
        #pragma unroll
        for (int o = 4; o > 0; o >>= 1) s2 += __shfl_xor_sync(0xffffffffu, s2, o);
        if (tid == 0) red[0] = s2;
    }
    __syncthreads();
    const float rstd = rsqrtf(red[0] * (1.f/1536.f) + 1e-5f);
    #pragma unroll
    for (int i = 0; i < 6; i++) {
        int c = tid + i*256;
        yrow[c] = v[i] * rstd * norm_w[c];
    }
}

// =================================================================
extern "C" void kernel_launch(void* const* d_in, const int* in_sizes, int n_in,
                              void* d_out, int out_size)
{
    const float* feature   = (const float*)d_in[0];
    const float* in_proj_w = (const float*)d_in[1];
    const float* conv_w    = (const float*)d_in[2];
    const float* conv_b    = (const float*)d_in[3];
    const float* dt_bias   = (const float*)d_in[4];
    const float* A_log     = (const float*)d_in[5];
    const float* Dvec      = (const float*)d_in[6];
    const float* norm_w    = (const float*)d_in[7];
    const float* out_projw = (const float*)d_in[8];
    const float* gate1     = (const float*)d_in[9];
    float* out = (float*)d_out;

    float *zx, *y;
    cudaGetSymbolAddress((void**)&zx, g_zxbcdt);
    cudaGetSymbolAddress((void**)&y,  g_y);

    dim3 blk(256);

    // in_proj: [8192,3352] = feature[8192,768] @ in_proj_w[3352,768]^T
    gemm_nt<<<dim3((DPROJ + 63)/64, ROWS/128), blk>>>(
        feature, in_proj_w, zx, ROWS, DPROJ, DMODEL, nullptr);

    // causal depthwise conv + silu
    conv_silu_kernel<<<(int)(((long)ROWS * CONVDIM) / 256), blk>>>(conv_w, conv_b);

    // dt / dA
    dt_kernel<<<(ROWS * NHEADS) / 256, blk>>>(dt_bias, A_log);

    // sequential scan
    scan_kernel<<<BATCH * NHEADS, blk>>>(Dvec);

    // gating + RMSNorm (in place on g_y)
    gate_norm_kernel<<<ROWS, blk>>>(norm_w);

    // out_proj: out[8192,768] = g_y[8192,1536] @ out_proj_w[768,1536]^T, * sigmoid(gate1)
    gemm_nt<<<dim3(DMODEL/64, ROWS/128), blk>>>(
        y, out_projw, out, ROWS, DMODEL, DINNER, gate1);
}

// round 2
// speedup vs baseline: 1.3140x; 1.3140x over previous
#include <cuda_runtime.h>
#include <math.h>
#include <stdint.h>

#define BATCH   4
#define LSEQ    2048
#define ROWS    (BATCH*LSEQ)      // 8192
#define DMODEL  768
#define DINNER  1536
#define NHEADS  24
#define HEADDIM 64
#define DSTATE  128
#define CONVDIM 1792
#define DPROJ   3352              // 2*DINNER + 2*DSTATE + NHEADS

// -------- scratch (device globals; no allocation allowed) --------
__device__ float g_zxbcdt[(size_t)ROWS * DPROJ];   // in_proj output
__device__ float g_xBC[(size_t)ROWS * CONVDIM];    // conv+silu output
__device__ float g_dt[ROWS * NHEADS];
__device__ float g_dA[ROWS * NHEADS];
__device__ float g_y[(size_t)ROWS * DINNER];       // scan output -> gated/normed

// =================================================================
// TF32 tensor-core GEMM (NT): C[M,N] = A[M,K] * B[N,K]^T
// BM=128, BN=128, BK=16, 256 threads (8 warps, 2x4), warp tile 64x32
// cp.async 2-stage pipeline, smem stride 20 (conflict-free frag loads)
// =================================================================
#define BM 128
#define BN 128
#define BKT 16

__device__ __forceinline__ uint32_t f2tf32(float x) {
    uint32_t r;
    asm("cvt.rna.tf32.f32 %0, %1;" : "=r"(r) : "f"(x));
    return r;
}

#define CPA16(dst, src, valid) \
    asm volatile("cp.async.cg.shared.global [%0], [%1], 16, %2;\n" \
                 :: "r"(dst), "l"(src), "r"((valid) ? 16 : 0))

#define MMA_TF32(d, a, b) \
    asm volatile("mma.sync.aligned.m16n8k8.row.col.f32.tf32.tf32.f32 " \
                 "{%0,%1,%2,%3},{%4,%5,%6,%7},{%8,%9},{%0,%1,%2,%3};\n" \
                 : "+f"((d)[0]), "+f"((d)[1]), "+f"((d)[2]), "+f"((d)[3]) \
                 : "r"((a)[0]), "r"((a)[1]), "r"((a)[2]), "r"((a)[3]), \
                   "r"((b)[0]), "r"((b)[1]))

__global__ __launch_bounds__(256) void gemm_tf32(
    const float* __restrict__ A, const float* __restrict__ B,
    float* __restrict__ C, int M, int N, int K,
    const float* __restrict__ gate)
{
    __shared__ float As[2][BM][20];
    __shared__ float Bs[2][BN][20];

    const int tid  = threadIdx.x;
    const int lane = tid & 31;
    const int warp = tid >> 5;
    const int wm   = warp >> 2;      // 0..1
    const int wn   = warp & 3;       // 0..3
    const int m0   = blockIdx.y * BM;
    const int n0   = blockIdx.x * BN;

    // ---- load mapping: each thread cp.asyncs rows lr and lr+64 at k-col lc ----
    const int lr = tid >> 2;        // 0..63
    const int lc = (tid & 3) * 4;   // 0,4,8,12

    const float* Ag0 = A + (size_t)(m0 + lr) * K + lc;
    const float* Ag1 = Ag0 + (size_t)64 * K;
    const bool  bv0 = (n0 + lr) < N;
    const bool  bv1 = (n0 + lr + 64) < N;
    const int   br0 = min(n0 + lr, N - 1);
    const int   br1 = min(n0 + lr + 64, N - 1);
    const float* Bg0 = B + (size_t)br0 * K + lc;
    const float* Bg1 = B + (size_t)br1 * K + lc;

    float acc[4][4][4];
    #pragma unroll
    for (int i = 0; i < 4; i++)
        #pragma unroll
        for (int j = 0; j < 4; j++)
            #pragma unroll
            for (int r = 0; r < 4; r++) acc[i][j][r] = 0.f;

    const int KT = K / BKT;

    // prolog: stage 0
    {
        uint32_t sA0 = (uint32_t)__cvta_generic_to_shared(&As[0][lr][lc]);
        uint32_t sA1 = (uint32_t)__cvta_generic_to_shared(&As[0][lr + 64][lc]);
        uint32_t sB0 = (uint32_t)__cvta_generic_to_shared(&Bs[0][lr][lc]);
        uint32_t sB1 = (uint32_t)__cvta_generic_to_shared(&Bs[0][lr + 64][lc]);
        CPA16(sA0, Ag0, true);
        CPA16(sA1, Ag1, true);
        CPA16(sB0, Bg0, bv0);
        CPA16(sB1, Bg1, bv1);
        asm volatile("cp.async.commit_group;\n" ::: "memory");
    }

    for (int kt = 0; kt < KT; kt++) {
        const int st = kt & 1;
        asm volatile("cp.async.wait_group 0;\n" ::: "memory");
        __syncthreads();

        if (kt + 1 < KT) {
            const int ns = st ^ 1;
            const size_t ko = (size_t)(kt + 1) * BKT;
            uint32_t sA0 = (uint32_t)__cvta_generic_to_shared(&As[ns][lr][lc]);
            uint32_t sA1 = (uint32_t)__cvta_generic_to_shared(&As[ns][lr + 64][lc]);
            uint32_t sB0 = (uint32_t)__cvta_generic_to_shared(&Bs[ns][lr][lc]);
            uint32_t sB1 = (uint32_t)__cvta_generic_to_shared(&Bs[ns][lr + 64][lc]);
            CPA16(sA0, Ag0 + ko, true);
            CPA16(sA1, Ag1 + ko, true);
            CPA16(sB0, Bg0 + ko, bv0);
            CPA16(sB1, Bg1 + ko, bv1);
            asm volatile("cp.async.commit_group;\n" ::: "memory");
        }

        // compute on stage st
        #pragma unroll
        for (int kk = 0; kk < BKT; kk += 8) {
            uint32_t a[4][4], b[4][2];
            const int qr = lane >> 2;        // 0..7
            const int qc = kk + (lane & 3);  // k offset
            #pragma unroll
            for (int mf = 0; mf < 4; mf++) {
                const int r = wm * 64 + mf * 16 + qr;
                a[mf][0] = f2tf32(As[st][r][qc]);
                a[mf][1] = f2tf32(As[st][r + 8][qc]);
                a[mf][2] = f2tf32(As[st][r][qc + 4]);
                a[mf][3] = f2tf32(As[st][r + 8][qc + 4]);
            }
            #pragma unroll
            for (int nf = 0; nf < 4; nf++) {
                const int r = wn * 32 + nf * 8 + qr;
                b[nf][0] = f2tf32(Bs[st][r][qc]);
                b[nf][1] = f2tf32(Bs[st][r][qc + 4]);
            }
            #pragma unroll
            for (int mf = 0; mf < 4; mf++)
                #pragma unroll
                for (int nf = 0; nf < 4; nf++)
                    MMA_TF32(acc[mf][nf], a[mf], b[nf]);
        }
    }

    float scale = 1.f;
    if (gate) { float g = *gate; scale = 1.f / (1.f + expf(-g)); }

    #pragma unroll
    for (int mf = 0; mf < 4; mf++) {
        const int r = m0 + wm * 64 + mf * 16 + (lane >> 2);
        #pragma unroll
        for (int nf = 0; nf < 4; nf++) {
            const int c = n0 + wn * 32 + nf * 8 + (lane & 3) * 2;
            if (c < N) {
                float2 v0 = make_float2(acc[mf][nf][0] * scale, acc[mf][nf][1] * scale);
                float2 v1 = make_float2(acc[mf][nf][2] * scale, acc[mf][nf][3] * scale);
                *(float2*)&C[(size_t)r * N + c]       = v0;
                *(float2*)&C[(size_t)(r + 8) * N + c] = v1;
            }
        }
    }
}

// =================================================================
// Causal depthwise conv1d (width 4) + bias + SiLU on xBC slice
// =================================================================
__global__ __launch_bounds__(256) void conv_silu_kernel(
    const float* __restrict__ conv_w, const float* __restrict__ conv_b)
{
    const long idx = (long)blockIdx.x * 256 + threadIdx.x;  // < ROWS*CONVDIM
    const int  c   = (int)(idx % CONVDIM);
    const long row = idx / CONVDIM;
    const int  l   = (int)(row % LSEQ);

    float acc = conv_b[c];
    const float w0 = conv_w[c*4+0], w1 = conv_w[c*4+1];
    const float w2 = conv_w[c*4+2], w3 = conv_w[c*4+3];
    const float* base = g_zxbcdt + (size_t)row * DPROJ + DINNER + c;
    if (l >= 3) acc = fmaf(base[-3*DPROJ], w0, acc);
    if (l >= 2) acc = fmaf(base[-2*DPROJ], w1, acc);
    if (l >= 1) acc = fmaf(base[-1*DPROJ], w2, acc);
    acc = fmaf(base[0], w3, acc);
    g_xBC[idx] = acc / (1.f + expf(-acc));  // silu
}

// =================================================================
// dt = softplus(dt_raw + dt_bias), dA = exp(dt * -exp(A_log))
// =================================================================
__global__ __launch_bounds__(256) void dt_kernel(
    const float* __restrict__ dt_bias, const float* __restrict__ A_log)
{
    const int idx = blockIdx.x * 256 + threadIdx.x;  // < ROWS*NHEADS
    const int h   = idx % NHEADS;
    const int row = idx / NHEADS;
    float v  = g_zxbcdt[(size_t)row * DPROJ + (DINNER + CONVDIM) + h] + dt_bias[h];
    float sp = (v > 20.f) ? v : log1pf(expf(v));
    g_dt[idx] = sp;
    g_dA[idx] = expf(-expf(A_log[h]) * sp);
}

// =================================================================
// Sequential SSM scan: one block per (b, h). 256 threads.
// =================================================================
__global__ __launch_bounds__(256) void scan_kernel(const float* __restrict__ Dvec)
{
    const int bh = blockIdx.x;
    const int b  = bh / NHEADS, h = bh % NHEADS;
    const int tid = threadIdx.x;
    const int p = tid >> 2, j = tid & 3;

    __shared__ float sh[2][320];   // [0..63]=x(head), [64..191]=B, [192..319]=C
    float hreg[32];
    #pragma unroll
    for (int k = 0; k < 32; k++) hreg[k] = 0.f;

    const float Dh = Dvec[h];
    const size_t rowbase = (size_t)b * LSEQ;
    const int c0 = (tid < 64) ? (h*HEADDIM + tid) : (1472 + tid);
    const int c1 = 1472 + tid + 256;

    { // preload t=0
        const float* r = g_xBC + rowbase * CONVDIM;
        sh[0][tid] = r[c0];
        if (tid < 64) sh[0][tid+256] = r[c1];
    }

    for (int t = 0; t < LSEQ; t++) {
        float r0 = 0.f, r1 = 0.f;
        if (t + 1 < LSEQ) {
            const float* r = g_xBC + (rowbase + t + 1) * CONVDIM;
            r0 = r[c0];
            if (tid < 64) r1 = r[c1];
        }
        const float dtv = g_dt[(rowbase + t)*NHEADS + h];
        const float dAv = g_dA[(rowbase + t)*NHEADS + h];
        __syncthreads();

        const float* s   = sh[t & 1];
        const float  xp  = s[p];
        const float  coef = dtv * xp;
        const float* Bsh = s + 64  + j*32;
        const float* Csh = s + 192 + j*32;
        float acc = 0.f;
        #pragma unroll
        for (int k = 0; k < 32; k++) {
            hreg[k] = fmaf(hreg[k], dAv, coef * Bsh[k]);
            acc     = fmaf(hreg[k], Csh[k], acc);
        }
        acc += __shfl_down_sync(0xffffffffu, acc, 2);
        acc += __shfl_down_sync(0xffffffffu, acc, 1);
        if (j == 0)
            g_y[(rowbase + t)*DINNER + h*HEADDIM + p] = acc + Dh * xp;

        if (t + 1 < LSEQ) {
            float* sn = sh[(t+1) & 1];
            sn[tid] = r0;
            if (tid < 64) sn[tid+256] = r1;
        }
    }
}

// =================================================================
// y = y * silu(z); y = y * rsqrt(mean(y^2)+eps) * norm_w   (in place)
// =================================================================
__global__ __launch_bounds__(256) void gate_norm_kernel(const float* __restrict__ norm_w)
{
    const int row = blockIdx.x;
    const int tid = threadIdx.x;
    const float* zrow = g_zxbcdt + (size_t)row * DPROJ;   // z = cols [0,1536)
    float* yrow = g_y + (size_t)row * DINNER;

    float v[6];
    float ss = 0.f;
    #pragma unroll
    for (int i = 0; i < 6; i++) {
        int c = tid + i*256;
        float z  = zrow[c];
        float yg = yrow[c] * (z / (1.f + expf(-z)));
        v[i] = yg;
        ss += yg * yg;
    }
    #pragma unroll
    for (int o = 16; o > 0; o >>= 1) ss += __shfl_xor_sync(0xffffffffu, ss, o);
    __shared__ float red[8];
    if ((tid & 31) == 0) red[tid >> 5] = ss;
    __syncthreads();
    if (tid < 32) {
        float s2 = (tid < 8) ? red[tid] : 0.f;
        #pragma unroll
        for (int o = 4; o > 0; o >>= 1) s2 += __shfl_xor_sync(0xffffffffu, s2, o);
        if (tid == 0) red[0] = s2;
    }
    __syncthreads();
    const float rstd = rsqrtf(red[0] * (1.f/1536.f) + 1e-5f);
    #pragma unroll
    for (int i = 0; i < 6; i++) {
        int c = tid + i*256;
        yrow[c] = v[i] * rstd * norm_w[c];
    }
}

// =================================================================
extern "C" void kernel_launch(void* const* d_in, const int* in_sizes, int n_in,
                              void* d_out, int out_size)
{
    const float* feature   = (const float*)d_in[0];
    const float* in_proj_w = (const float*)d_in[1];
    const float* conv_w    = (const float*)d_in[2];
    const float* conv_b    = (const float*)d_in[3];
    const float* dt_bias   = (const float*)d_in[4];
    const float* A_log     = (const float*)d_in[5];
    const float* Dvec      = (const float*)d_in[6];
    const float* norm_w    = (const float*)d_in[7];
    const float* out_projw = (const float*)d_in[8];
    const float* gate1     = (const float*)d_in[9];
    float* out = (float*)d_out;

    float *zx, *y;
    cudaGetSymbolAddress((void**)&zx, g_zxbcdt);
    cudaGetSymbolAddress((void**)&y,  g_y);

    dim3 blk(256);

    // in_proj: [8192,3352] = feature[8192,768] @ in_proj_w[3352,768]^T
    gemm_tf32<<<dim3((DPROJ + BN - 1)/BN, ROWS/BM), blk>>>(
        feature, in_proj_w, zx, ROWS, DPROJ, DMODEL, nullptr);

    // causal depthwise conv + silu
    conv_silu_kernel<<<(int)(((long)ROWS * CONVDIM) / 256), blk>>>(conv_w, conv_b);

    // dt / dA
    dt_kernel<<<(ROWS * NHEADS) / 256, blk>>>(dt_bias, A_log);

    // sequential scan
    scan_kernel<<<BATCH * NHEADS, blk>>>(Dvec);

    // gating + RMSNorm (in place on g_y)
    gate_norm_kernel<<<ROWS, blk>>>(norm_w);

    // out_proj: out[8192,768] = g_y[8192,1536] @ out_proj_w[768,1536]^T, * sigmoid(gate1)
    gemm_tf32<<<dim3(DMODEL/BN, ROWS/BM), blk>>>(
        y, out_projw, out, ROWS, DMODEL, DINNER, gate1);
}

// round 3
// speedup vs baseline: 1.3777x; 1.0485x over previous
#include <cuda_runtime.h>
#include <math.h>
#include <stdint.h>

#define BATCH   4
#define LSEQ    2048
#define ROWS    (BATCH*LSEQ)      // 8192
#define DMODEL  768
#define DINNER  1536
#define NHEADS  24
#define HEADDIM 64
#define DSTATE  128
#define CONVDIM 1792
#define DPROJ   3352              // 2*DINNER + 2*DSTATE + NHEADS

#define NSEG    16
#define SEGLEN  (LSEQ/NSEG)       // 128
#define STATESZ (HEADDIM*DSTATE)  // 8192

// -------- scratch (device globals; no allocation allowed) --------
__device__ float g_zxbcdt[(size_t)ROWS * DPROJ];   // in_proj output
__device__ float g_xBC[(size_t)ROWS * CONVDIM];    // conv+silu output
__device__ float g_dt[ROWS * NHEADS];
__device__ float g_dA[ROWS * NHEADS];
__device__ float g_y[(size_t)ROWS * DINNER];       // scan output -> gated/normed
__device__ float g_states[(size_t)BATCH*NHEADS*NSEG*STATESZ];  // segment end states
__device__ float g_hstart[(size_t)BATCH*NHEADS*NSEG*STATESZ];  // segment start states

// =================================================================
// TF32 tensor-core GEMM (NT): C[M,N] = A[M,K] * B[N,K]^T
// =================================================================
#define BM 128
#define BN 128
#define BKT 16

__device__ __forceinline__ uint32_t f2tf32(float x) {
    uint32_t r;
    asm("cvt.rna.tf32.f32 %0, %1;" : "=r"(r) : "f"(x));
    return r;
}

#define CPA16(dst, src, valid) \
    asm volatile("cp.async.cg.shared.global [%0], [%1], 16, %2;\n" \
                 :: "r"(dst), "l"(src), "r"((valid) ? 16 : 0))

#define MMA_TF32(d, a, b) \
    asm volatile("mma.sync.aligned.m16n8k8.row.col.f32.tf32.tf32.f32 " \
                 "{%0,%1,%2,%3},{%4,%5,%6,%7},{%8,%9},{%0,%1,%2,%3};\n" \
                 : "+f"((d)[0]), "+f"((d)[1]), "+f"((d)[2]), "+f"((d)[3]) \
                 : "r"((a)[0]), "r"((a)[1]), "r"((a)[2]), "r"((a)[3]), \
                   "r"((b)[0]), "r"((b)[1]))

__global__ __launch_bounds__(256) void gemm_tf32(
    const float* __restrict__ A, const float* __restrict__ B,
    float* __restrict__ C, int M, int N, int K,
    const float* __restrict__ gate)
{
    __shared__ float As[2][BM][20];
    __shared__ float Bs[2][BN][20];

    const int tid  = threadIdx.x;
    const int lane = tid & 31;
    const int warp = tid >> 5;
    const int wm   = warp >> 2;
    const int wn   = warp & 3;
    const int m0   = blockIdx.y * BM;
    const int n0   = blockIdx.x * BN;

    const int lr = tid >> 2;
    const int lc = (tid & 3) * 4;

    const float* Ag0 = A + (size_t)(m0 + lr) * K + lc;
    const float* Ag1 = Ag0 + (size_t)64 * K;
    const bool  bv0 = (n0 + lr) < N;
    const bool  bv1 = (n0 + lr + 64) < N;
    const int   br0 = min(n0 + lr, N - 1);
    const int   br1 = min(n0 + lr + 64, N - 1);
    const float* Bg0 = B + (size_t)br0 * K + lc;
    const float* Bg1 = B + (size_t)br1 * K + lc;

    float acc[4][4][4];
    #pragma unroll
    for (int i = 0; i < 4; i++)
        #pragma unroll
        for (int j = 0; j < 4; j++)
            #pragma unroll
            for (int r = 0; r < 4; r++) acc[i][j][r] = 0.f;

    const int KT = K / BKT;

    {
        uint32_t sA0 = (uint32_t)__cvta_generic_to_shared(&As[0][lr][lc]);
        uint32_t sA1 = (uint32_t)__cvta_generic_to_shared(&As[0][lr + 64][lc]);
        uint32_t sB0 = (uint32_t)__cvta_generic_to_shared(&Bs[0][lr][lc]);
        uint32_t sB1 = (uint32_t)__cvta_generic_to_shared(&Bs[0][lr + 64][lc]);
        CPA16(sA0, Ag0, true);
        CPA16(sA1, Ag1, true);
        CPA16(sB0, Bg0, bv0);
        CPA16(sB1, Bg1, bv1);
        asm volatile("cp.async.commit_group;\n" ::: "memory");
    }

    for (int kt = 0; kt < KT; kt++) {
        const int st = kt & 1;
        asm volatile("cp.async.wait_group 0;\n" ::: "memory");
        __syncthreads();

        if (kt + 1 < KT) {
            const int ns = st ^ 1;
            const size_t ko = (size_t)(kt + 1) * BKT;
            uint32_t sA0 = (uint32_t)__cvta_generic_to_shared(&As[ns][lr][lc]);
            uint32_t sA1 = (uint32_t)__cvta_generic_to_shared(&As[ns][lr + 64][lc]);
            uint32_t sB0 = (uint32_t)__cvta_generic_to_shared(&Bs[ns][lr][lc]);
            uint32_t sB1 = (uint32_t)__cvta_generic_to_shared(&Bs[ns][lr + 64][lc]);
            CPA16(sA0, Ag0 + ko, true);
            CPA16(sA1, Ag1 + ko, true);
            CPA16(sB0, Bg0 + ko, bv0);
            CPA16(sB1, Bg1 + ko, bv1);
            asm volatile("cp.async.commit_group;\n" ::: "memory");
        }

        #pragma unroll
        for (int kk = 0; kk < BKT; kk += 8) {
            uint32_t a[4][4], b[4][2];
            const int qr = lane >> 2;
            const int qc = kk + (lane & 3);
            #pragma unroll
            for (int mf = 0; mf < 4; mf++) {
                const int r = wm * 64 + mf * 16 + qr;
                a[mf][0] = f2tf32(As[st][r][qc]);
                a[mf][1] = f2tf32(As[st][r + 8][qc]);
                a[mf][2] = f2tf32(As[st][r][qc + 4]);
                a[mf][3] = f2tf32(As[st][r + 8][qc + 4]);
            }
            #pragma unroll
            for (int nf = 0; nf < 4; nf++) {
                const int r = wn * 32 + nf * 8 + qr;
                b[nf][0] = f2tf32(Bs[st][r][qc]);
                b[nf][1] = f2tf32(Bs[st][r][qc + 4]);
            }
            #pragma unroll
            for (int mf = 0; mf < 4; mf++)
                #pragma unroll
                for (int nf = 0; nf < 4; nf++)
                    MMA_TF32(acc[mf][nf], a[mf], b[nf]);
        }
    }

    float scale = 1.f;
    if (gate) { float g = *gate; scale = 1.f / (1.f + expf(-g)); }

    #pragma unroll
    for (int mf = 0; mf < 4; mf++) {
        const int r = m0 + wm * 64 + mf * 16 + (lane >> 2);
        #pragma unroll
        for (int nf = 0; nf < 4; nf++) {
            const int c = n0 + wn * 32 + nf * 8 + (lane & 3) * 2;
            if (c < N) {
                float2 v0 = make_float2(acc[mf][nf][0] * scale, acc[mf][nf][1] * scale);
                float2 v1 = make_float2(acc[mf][nf][2] * scale, acc[mf][nf][3] * scale);
                *(float2*)&C[(size_t)r * N + c]       = v0;
                *(float2*)&C[(size_t)(r + 8) * N + c] = v1;
            }
        }
    }
}

// =================================================================
// Causal depthwise conv1d (width 4) + bias + SiLU on xBC slice
// =================================================================
__global__ __launch_bounds__(256) void conv_silu_kernel(
    const float* __restrict__ conv_w, const float* __restrict__ conv_b)
{
    const long idx = (long)blockIdx.x * 256 + threadIdx.x;
    const int  c   = (int)(idx % CONVDIM);
    const long row = idx / CONVDIM;
    const int  l   = (int)(row % LSEQ);

    float acc = conv_b[c];
    const float w0 = conv_w[c*4+0], w1 = conv_w[c*4+1];
    const float w2 = conv_w[c*4+2], w3 = conv_w[c*4+3];
    const float* base = g_zxbcdt + (size_t)row * DPROJ + DINNER + c;
    if (l >= 3) acc = fmaf(base[-3*DPROJ], w0, acc);
    if (l >= 2) acc = fmaf(base[-2*DPROJ], w1, acc);
    if (l >= 1) acc = fmaf(base[-1*DPROJ], w2, acc);
    acc = fmaf(base[0], w3, acc);
    g_xBC[idx] = acc / (1.f + expf(-acc));
}

// =================================================================
// dt = softplus(dt_raw + dt_bias), dA = exp(dt * -exp(A_log))
// =================================================================
__global__ __launch_bounds__(256) void dt_kernel(
    const float* __restrict__ dt_bias, const float* __restrict__ A_log)
{
    const int idx = blockIdx.x * 256 + threadIdx.x;
    const int h   = idx % NHEADS;
    const int row = idx / NHEADS;
    float v  = g_zxbcdt[(size_t)row * DPROJ + (DINNER + CONVDIM) + h] + dt_bias[h];
    float sp = (v > 20.f) ? v : log1pf(expf(v));
    g_dt[idx] = sp;
    g_dA[idx] = expf(-expf(A_log[h]) * sp);
}

// =================================================================
// Segmented SSM scan.
// Pass 1 (FIRST=true): per-segment scan from h=0, write end state only.
// Pass 3 (FIRST=false): per-segment scan from g_hstart, write y.
// grid = BATCH*NHEADS*NSEG blocks, 256 threads: p=tid>>2, j=tid&3.
// =================================================================
template<bool FIRST>
__global__ __launch_bounds__(256) void scan_seg_kernel(const float* __restrict__ Dvec)
{
    const int blk = blockIdx.x;
    const int bh  = blk >> 4;          // / NSEG
    const int seg = blk & (NSEG - 1);
    const int b   = bh / NHEADS, h = bh % NHEADS;
    const int tid = threadIdx.x;
    const int p = tid >> 2, j = tid & 3;
    const int t0 = seg * SEGLEN;

    __shared__ float sh[2][320];   // [0..63]=x(head), [64..191]=B, [192..319]=C
    float hreg[32];
    if (FIRST) {
        #pragma unroll
        for (int k = 0; k < 32; k++) hreg[k] = 0.f;
    } else {
        const size_t base = ((size_t)bh * NSEG + seg) * STATESZ + p * DSTATE + j * 32;
        #pragma unroll
        for (int k = 0; k < 32; k++) hreg[k] = g_hstart[base + k];
    }

    const float Dh = Dvec[h];
    const size_t rowbase = (size_t)b * LSEQ;
    const int c0 = (tid < 64) ? (h*HEADDIM + tid) : (1472 + tid);
    const int c1 = 1472 + tid + 256;
    const bool ld0 = FIRST ? (tid < 192) : true;   // pass1 skips C
    const bool ld1 = (!FIRST) && (tid < 64);

    { // preload first step of segment (t0 is even -> buffer 0)
        const float* r = g_xBC + (rowbase + t0) * CONVDIM;
        sh[0][tid] = ld0 ? r[c0] : 0.f;
        if (tid < 64) sh[0][tid+256] = ld1 ? r[c1] : 0.f;
    }

    const int tend = t0 + SEGLEN;
    for (int t = t0; t < tend; t++) {
        float r0 = 0.f, r1 = 0.f;
        if (t + 1 < tend) {
            const float* r = g_xBC + (rowbase + t + 1) * CONVDIM;
            if (ld0) r0 = r[c0];
            if (ld1) r1 = r[c1];
        }
        const float dtv = g_dt[(rowbase + t)*NHEADS + h];
        const float dAv = g_dA[(rowbase + t)*NHEADS + h];
        __syncthreads();

        const float* s   = sh[t & 1];
        const float  xp  = s[p];
        const float  coef = dtv * xp;
        const float4* B4 = (const float4*)(s + 64  + j*32);

        if (FIRST) {
            #pragma unroll
            for (int k4 = 0; k4 < 8; k4++) {
                float4 b4 = B4[k4];
                hreg[k4*4+0] = fmaf(hreg[k4*4+0], dAv, coef * b4.x);
                hreg[k4*4+1] = fmaf(hreg[k4*4+1], dAv, coef * b4.y);
                hreg[k4*4+2] = fmaf(hreg[k4*4+2], dAv, coef * b4.z);
                hreg[k4*4+3] = fmaf(hreg[k4*4+3], dAv, coef * b4.w);
            }
        } else {
            const float4* C4 = (const float4*)(s + 192 + j*32);
            float acc = 0.f;
            #pragma unroll
            for (int k4 = 0; k4 < 8; k4++) {
                float4 b4 = B4[k4];
                float4 c4 = C4[k4];
                hreg[k4*4+0] = fmaf(hreg[k4*4+0], dAv, coef * b4.x);
                acc = fmaf(hreg[k4*4+0], c4.x, acc);
                hreg[k4*4+1] = fmaf(hreg[k4*4+1], dAv, coef * b4.y);
                acc = fmaf(hreg[k4*4+1], c4.y, acc);
                hreg[k4*4+2] = fmaf(hreg[k4*4+2], dAv, coef * b4.z);
                acc = fmaf(hreg[k4*4+2], c4.z, acc);
                hreg[k4*4+3] = fmaf(hreg[k4*4+3], dAv, coef * b4.w);
                acc = fmaf(hreg[k4*4+3], c4.w, acc);
            }
            acc += __shfl_down_sync(0xffffffffu, acc, 2);
            acc += __shfl_down_sync(0xffffffffu, acc, 1);
            if (j == 0)
                g_y[(rowbase + t)*DINNER + h*HEADDIM + p] = acc + Dh * xp;
        }

        if (t + 1 < tend) {
            float* sn = sh[(t+1) & 1];
            sn[tid] = r0;
            if (tid < 64) sn[tid+256] = r1;
        }
    }

    if (FIRST) {
        const size_t base = ((size_t)bh * NSEG + seg) * STATESZ + p * DSTATE + j * 32;
        #pragma unroll
        for (int k = 0; k < 32; k++) g_states[base + k] = hreg[k];
    }
}

// =================================================================
// Combine: h_start[seg+1] = E_seg * h_start[seg] + S_seg, per (b,h).
// E_seg = exp(-exp(A_log) * sum(dt over segment)). grid=96, 256 thr.
// =================================================================
__global__ __launch_bounds__(256) void combine_kernel(const float* __restrict__ A_log)
{
    const int bh = blockIdx.x;
    const int b = bh / NHEADS, h = bh % NHEADS;
    const int tid = threadIdx.x;

    __shared__ float part[256];
    __shared__ float Esh[NSEG];

    { // segment dt sums: thread (k=tid>>4, i=tid&15) sums 8 steps
        const int k = tid >> 4, i = tid & 15;
        float s = 0.f;
        const size_t base = ((size_t)b*LSEQ + k*SEGLEN + i*8)*NHEADS + h;
        #pragma unroll
        for (int t = 0; t < 8; t++) s += g_dt[base + (size_t)t*NHEADS];
        part[tid] = s;
    }
    __syncthreads();
    if (tid < NSEG) {
        float s = 0.f;
        #pragma unroll
        for (int i = 0; i < 16; i++) s += part[tid*16 + i];
        Esh[tid] = expf(-expf(A_log[h]) * s);
    }
    __syncthreads();

    float hs[32];
    #pragma unroll
    for (int k2 = 0; k2 < 32; k2++) hs[k2] = 0.f;

    for (int seg = 0; seg < NSEG; seg++) {
        const size_t base = ((size_t)bh*NSEG + seg)*STATESZ;
        const float E = Esh[seg];
        #pragma unroll
        for (int k2 = 0; k2 < 32; k2++) {
            const size_t e = base + k2*256 + tid;
            g_hstart[e] = hs[k2];
            hs[k2] = fmaf(hs[k2], E, g_states[e]);
        }
    }
}

// =================================================================
// y = y * silu(z); y = y * rsqrt(mean(y^2)+eps) * norm_w   (in place)
// =================================================================
__global__ __launch_bounds__(256) void gate_norm_kernel(const float* __restrict__ norm_w)
{
    const int row = blockIdx.x;
    const int tid = threadIdx.x;
    const float* zrow = g_zxbcdt + (size_t)row * DPROJ;
    float* yrow = g_y + (size_t)row * DINNER;

    float v[6];
    float ss = 0.f;
    #pragma unroll
    for (int i = 0; i < 6; i++) {
        int c = tid + i*256;
        float z  = zrow[c];
        float yg = yrow[c] * (z / (1.f + expf(-z)));
        v[i] = yg;
        ss += yg * yg;
    }
    #pragma unroll
    for (int o = 16; o > 0; o >>= 1) ss += __shfl_xor_sync(0xffffffffu, ss, o);
    __shared__ float red[8];
    if ((tid & 31) == 0) red[tid >> 5] = ss;
    __syncthreads();
    if (tid < 32) {
        float s2 = (tid < 8) ? red[tid] : 0.f;
        #pragma unroll
        for (int o = 4; o > 0; o >>= 1) s2 += __shfl_xor_sync(0xffffffffu, s2, o);
        if (tid == 0) red[0] = s2;
    }
    __syncthreads();
    const float rstd = rsqrtf(red[0] * (1.f/1536.f) + 1e-5f);
    #pragma unroll
    for (int i = 0; i < 6; i++) {
        int c = tid + i*256;
        yrow[c] = v[i] * rstd * norm_w[c];
    }
}

// =================================================================
extern "C" void kernel_launch(void* const* d_in, const int* in_sizes, int n_in,
                              void* d_out, int out_size)
{
    const float* feature   = (const float*)d_in[0];
    const float* in_proj_w = (const float*)d_in[1];
    const float* conv_w    = (const float*)d_in[2];
    const float* conv_b    = (const float*)d_in[3];
    const float* dt_bias   = (const float*)d_in[4];
    const float* A_log     = (const float*)d_in[5];
    const float* Dvec      = (const float*)d_in[6];
    const float* norm_w    = (const float*)d_in[7];
    const float* out_projw = (const float*)d_in[8];
    const float* gate1     = (const float*)d_in[9];
    float* out = (float*)d_out;

    float *zx, *y;
    cudaGetSymbolAddress((void**)&zx, g_zxbcdt);
    cudaGetSymbolAddress((void**)&y,  g_y);

    dim3 blk(256);

    gemm_tf32<<<dim3((DPROJ + BN - 1)/BN, ROWS/BM), blk>>>(
        feature, in_proj_w, zx, ROWS, DPROJ, DMODEL, nullptr);

    conv_silu_kernel<<<(int)(((long)ROWS * CONVDIM) / 256), blk>>>(conv_w, conv_b);

    dt_kernel<<<(ROWS * NHEADS) / 256, blk>>>(dt_bias, A_log);

    scan_seg_kernel<true><<<BATCH * NHEADS * NSEG, blk>>>(Dvec);
    combine_kernel<<<BATCH * NHEADS, blk>>>(A_log);
    scan_seg_kernel<false><<<BATCH * NHEADS * NSEG, blk>>>(Dvec);

    gate_norm_kernel<<<ROWS, blk>>>(norm_w);

    gemm_tf32<<<dim3(DMODEL/BN, ROWS/BM), blk>>>(
        y, out_projw, out, ROWS, DMODEL, DINNER, gate1);
}

// round 4
// speedup vs baseline: 1.4063x; 1.0207x over previous
#include <cuda_runtime.h>
#include <math.h>
#include <stdint.h>

#define BATCH   4
#define LSEQ    2048
#define ROWS    (BATCH*LSEQ)      // 8192
#define DMODEL  768
#define DINNER  1536
#define NHEADS  24
#define HEADDIM 64
#define DSTATE  128
#define CONVDIM 1792
#define DPROJ   3352              // 2*DINNER + 2*DSTATE + NHEADS

#define NSEG    16
#define SEGLEN  (LSEQ/NSEG)       // 128
#define STATESZ (HEADDIM*DSTATE)  // 8192

// -------- scratch (device globals; no allocation allowed) --------
__device__ float g_zxbcdt[(size_t)ROWS * DPROJ];   // in_proj output
__device__ float g_xBC[(size_t)ROWS * CONVDIM];    // conv+silu output
__device__ float g_dt[ROWS * NHEADS];
__device__ float g_dA[ROWS * NHEADS];
__device__ float g_y[(size_t)ROWS * DINNER];       // scan output -> gated/normed
__device__ float g_states[(size_t)BATCH*NHEADS*NSEG*STATESZ];  // segment end states
__device__ float g_hstart[(size_t)BATCH*NHEADS*NSEG*STATESZ];  // segment start states

// =================================================================
// TF32 tensor-core GEMM (NT): C[M,N] = A[M,K] * B[N,K]^T
// =================================================================
#define BM 128
#define BN 128
#define BKT 16

__device__ __forceinline__ uint32_t f2tf32(float x) {
    uint32_t r;
    asm("cvt.rna.tf32.f32 %0, %1;" : "=r"(r) : "f"(x));
    return r;
}

#define CPA16(dst, src) \
    asm volatile("cp.async.cg.shared.global [%0], [%1], 16;\n" \
                 :: "r"(dst), "l"(src))
#define CPA16P(dst, src, valid) \
    asm volatile("cp.async.cg.shared.global [%0], [%1], 16, %2;\n" \
                 :: "r"(dst), "l"(src), "r"((valid) ? 16 : 0))

#define MMA_TF32(d, a, b) \
    asm volatile("mma.sync.aligned.m16n8k8.row.col.f32.tf32.tf32.f32 " \
                 "{%0,%1,%2,%3},{%4,%5,%6,%7},{%8,%9},{%0,%1,%2,%3};\n" \
                 : "+f"((d)[0]), "+f"((d)[1]), "+f"((d)[2]), "+f"((d)[3]) \
                 : "r"((a)[0]), "r"((a)[1]), "r"((a)[2]), "r"((a)[3]), \
                   "r"((b)[0]), "r"((b)[1]))

__global__ __launch_bounds__(256) void gemm_tf32(
    const float* __restrict__ A, const float* __restrict__ B,
    float* __restrict__ C, int M, int N, int K,
    const float* __restrict__ gate)
{
    __shared__ float As[2][BM][20];
    __shared__ float Bs[2][BN][20];

    const int tid  = threadIdx.x;
    const int lane = tid & 31;
    const int warp = tid >> 5;
    const int wm   = warp >> 2;
    const int wn   = warp & 3;
    const int m0   = blockIdx.y * BM;
    const int n0   = blockIdx.x * BN;

    const int lr = tid >> 2;
    const int lc = (tid & 3) * 4;

    const float* Ag0 = A + (size_t)(m0 + lr) * K + lc;
    const float* Ag1 = Ag0 + (size_t)64 * K;
    const bool  bv0 = (n0 + lr) < N;
    const bool  bv1 = (n0 + lr + 64) < N;
    const int   br0 = min(n0 + lr, N - 1);
    const int   br1 = min(n0 + lr + 64, N - 1);
    const float* Bg0 = B + (size_t)br0 * K + lc;
    const float* Bg1 = B + (size_t)br1 * K + lc;

    float acc[4][4][4];
    #pragma unroll
    for (int i = 0; i < 4; i++)
        #pragma unroll
        for (int j = 0; j < 4; j++)
            #pragma unroll
            for (int r = 0; r < 4; r++) acc[i][j][r] = 0.f;

    const int KT = K / BKT;

    {
        uint32_t sA0 = (uint32_t)__cvta_generic_to_shared(&As[0][lr][lc]);
        uint32_t sA1 = (uint32_t)__cvta_generic_to_shared(&As[0][lr + 64][lc]);
        uint32_t sB0 = (uint32_t)__cvta_generic_to_shared(&Bs[0][lr][lc]);
        uint32_t sB1 = (uint32_t)__cvta_generic_to_shared(&Bs[0][lr + 64][lc]);
        CPA16(sA0, Ag0);
        CPA16(sA1, Ag1);
        CPA16P(sB0, Bg0, bv0);
        CPA16P(sB1, Bg1, bv1);
        asm volatile("cp.async.commit_group;\n" ::: "memory");
    }

    for (int kt = 0; kt < KT; kt++) {
        const int st = kt & 1;
        asm volatile("cp.async.wait_group 0;\n" ::: "memory");
        __syncthreads();

        if (kt + 1 < KT) {
            const int ns = st ^ 1;
            const size_t ko = (size_t)(kt + 1) * BKT;
            uint32_t sA0 = (uint32_t)__cvta_generic_to_shared(&As[ns][lr][lc]);
            uint32_t sA1 = (uint32_t)__cvta_generic_to_shared(&As[ns][lr + 64][lc]);
            uint32_t sB0 = (uint32_t)__cvta_generic_to_shared(&Bs[ns][lr][lc]);
            uint32_t sB1 = (uint32_t)__cvta_generic_to_shared(&Bs[ns][lr + 64][lc]);
            CPA16(sA0, Ag0 + ko);
            CPA16(sA1, Ag1 + ko);
            CPA16P(sB0, Bg0 + ko, bv0);
            CPA16P(sB1, Bg1 + ko, bv1);
            asm volatile("cp.async.commit_group;\n" ::: "memory");
        }

        #pragma unroll
        for (int kk = 0; kk < BKT; kk += 8) {
            uint32_t a[4][4], b[4][2];
            const int qr = lane >> 2;
            const int qc = kk + (lane & 3);
            #pragma unroll
            for (int mf = 0; mf < 4; mf++) {
                const int r = wm * 64 + mf * 16 + qr;
                a[mf][0] = f2tf32(As[st][r][qc]);
                a[mf][1] = f2tf32(As[st][r + 8][qc]);
                a[mf][2] = f2tf32(As[st][r][qc + 4]);
                a[mf][3] = f2tf32(As[st][r + 8][qc + 4]);
            }
            #pragma unroll
            for (int nf = 0; nf < 4; nf++) {
                const int r = wn * 32 + nf * 8 + qr;
                b[nf][0] = f2tf32(Bs[st][r][qc]);
                b[nf][1] = f2tf32(Bs[st][r][qc + 4]);
            }
            #pragma unroll
            for (int mf = 0; mf < 4; mf++)
                #pragma unroll
                for (int nf = 0; nf < 4; nf++)
                    MMA_TF32(acc[mf][nf], a[mf], b[nf]);
        }
    }

    float scale = 1.f;
    if (gate) { float g = *gate; scale = 1.f / (1.f + expf(-g)); }

    #pragma unroll
    for (int mf = 0; mf < 4; mf++) {
        const int r = m0 + wm * 64 + mf * 16 + (lane >> 2);
        #pragma unroll
        for (int nf = 0; nf < 4; nf++) {
            const int c = n0 + wn * 32 + nf * 8 + (lane & 3) * 2;
            if (c < N) {
                float2 v0 = make_float2(acc[mf][nf][0] * scale, acc[mf][nf][1] * scale);
                float2 v1 = make_float2(acc[mf][nf][2] * scale, acc[mf][nf][3] * scale);
                *(float2*)&C[(size_t)r * N + c]       = v0;
                *(float2*)&C[(size_t)(r + 8) * N + c] = v1;
            }
        }
    }
}

// =================================================================
// Causal depthwise conv1d (width 4) + bias + SiLU on xBC slice
// =================================================================
__global__ __launch_bounds__(256) void conv_silu_kernel(
    const float* __restrict__ conv_w, const float* __restrict__ conv_b)
{
    const long idx = (long)blockIdx.x * 256 + threadIdx.x;
    const int  c   = (int)(idx % CONVDIM);
    const long row = idx / CONVDIM;
    const int  l   = (int)(row % LSEQ);

    float acc = conv_b[c];
    const float w0 = conv_w[c*4+0], w1 = conv_w[c*4+1];
    const float w2 = conv_w[c*4+2], w3 = conv_w[c*4+3];
    const float* base = g_zxbcdt + (size_t)row * DPROJ + DINNER + c;
    if (l >= 3) acc = fmaf(base[-3*DPROJ], w0, acc);
    if (l >= 2) acc = fmaf(base[-2*DPROJ], w1, acc);
    if (l >= 1) acc = fmaf(base[-1*DPROJ], w2, acc);
    acc = fmaf(base[0], w3, acc);
    g_xBC[idx] = acc / (1.f + expf(-acc));
}

// =================================================================
// dt = softplus(dt_raw + dt_bias), dA = exp(dt * -exp(A_log))
// =================================================================
__global__ __launch_bounds__(256) void dt_kernel(
    const float* __restrict__ dt_bias, const float* __restrict__ A_log)
{
    const int idx = blockIdx.x * 256 + threadIdx.x;
    const int h   = idx % NHEADS;
    const int row = idx / NHEADS;
    float v  = g_zxbcdt[(size_t)row * DPROJ + (DINNER + CONVDIM) + h] + dt_bias[h];
    float sp = (v > 20.f) ? v : log1pf(expf(v));
    g_dt[idx] = sp;
    g_dA[idx] = expf(-expf(A_log[h]) * sp);
}

// =================================================================
// Chunk end-state (closed form, replaces recurrent pass 1):
//   S[p][n] = sum_t w_t * x_t[p] * B_t[n],
//   w_t = dt_t * exp(-A * (Dseg - a_t)),  a_t = inclusive cumsum(dt)
// grid = BATCH*NHEADS*NSEG, 256 threads (p=tid>>2, j=tid&3, 32 accs)
// =================================================================
__global__ __launch_bounds__(256) void chunk_state_kernel(const float* __restrict__ A_log)
{
    const int blk = blockIdx.x;
    const int bh  = blk >> 4;
    const int seg = blk & (NSEG - 1);
    const int b   = bh / NHEADS, h = bh % NHEADS;
    const int tid = threadIdx.x;
    const int lane = tid & 31, warp = tid >> 5;
    const int p = tid >> 2, j = tid & 3;
    const int t0 = seg * SEGLEN;
    const size_t rowbase = (size_t)b * LSEQ;

    __shared__ float sw[SEGLEN];
    __shared__ float wsum[4];
    __shared__ float stile[8 * 192];   // 8 steps x (64 x*w | 128 B)

    // --- per-segment dt cumsum + weights ---
    float vdt = 0.f, s = 0.f;
    if (tid < SEGLEN) {
        vdt = g_dt[(rowbase + t0 + tid) * NHEADS + h];
        s = vdt;
        #pragma unroll
        for (int o = 1; o < 32; o <<= 1) {
            float nv = __shfl_up_sync(0xffffffffu, s, o);
            if (lane >= o) s += nv;
        }
        if (lane == 31) wsum[warp] = s;
    }
    __syncthreads();
    if (tid < SEGLEN) {
        float Dtot = wsum[0] + wsum[1] + wsum[2] + wsum[3];
        float pre = 0.f;
        for (int w2 = 0; w2 < warp; w2++) pre += wsum[w2];
        float a = s + pre;
        const float Aneg = -expf(A_log[h]);
        sw[tid] = vdt * expf(Aneg * (Dtot - a));
    }
    __syncthreads();

    float acc[32];
    #pragma unroll
    for (int k = 0; k < 32; k++) acc[k] = 0.f;

    for (int tg = 0; tg < SEGLEN / 8; tg++) {
        #pragma unroll
        for (int i = 0; i < 6; i++) {
            int e = tid + i * 256;              // < 1536
            int tt = e / 192, c = e % 192;
            int col = (c < 64) ? (h * HEADDIM + c) : (1472 + c);
            float v = g_xBC[(rowbase + t0 + tg*8 + tt) * CONVDIM + col];
            if (c < 64) v *= sw[tg*8 + tt];
            stile[tt * 192 + c] = v;
        }
        __syncthreads();
        #pragma unroll
        for (int tt = 0; tt < 8; tt++) {
            const float* bp = &stile[tt * 192];
            const float coef = bp[p];
            const float4* B4 = (const float4*)(bp + 64 + j * 32);
            #pragma unroll
            for (int k4 = 0; k4 < 8; k4++) {
                float4 b4 = B4[k4];
                acc[k4*4+0] = fmaf(coef, b4.x, acc[k4*4+0]);
                acc[k4*4+1] = fmaf(coef, b4.y, acc[k4*4+1]);
                acc[k4*4+2] = fmaf(coef, b4.z, acc[k4*4+2]);
                acc[k4*4+3] = fmaf(coef, b4.w, acc[k4*4+3]);
            }
        }
        __syncthreads();
    }

    const size_t base = ((size_t)bh * NSEG + seg) * STATESZ + p * DSTATE + j * 32;
    #pragma unroll
    for (int k = 0; k < 32; k++) g_states[base + k] = acc[k];
}

// =================================================================
// Combine: h_start[seg+1] = E_seg * h_start[seg] + S_seg, per (b,h).
// =================================================================
__global__ __launch_bounds__(256) void combine_kernel(const float* __restrict__ A_log)
{
    const int bh = blockIdx.x;
    const int b = bh / NHEADS, h = bh % NHEADS;
    const int tid = threadIdx.x;

    __shared__ float part[256];
    __shared__ float Esh[NSEG];

    {
        const int k = tid >> 4, i = tid & 15;
        float s = 0.f;
        const size_t base = ((size_t)b*LSEQ + k*SEGLEN + i*8)*NHEADS + h;
        #pragma unroll
        for (int t = 0; t < 8; t++) s += g_dt[base + (size_t)t*NHEADS];
        part[tid] = s;
    }
    __syncthreads();
    if (tid < NSEG) {
        float s = 0.f;
        #pragma unroll
        for (int i = 0; i < 16; i++) s += part[tid*16 + i];
        Esh[tid] = expf(-expf(A_log[h]) * s);
    }
    __syncthreads();

    float hs[32];
    #pragma unroll
    for (int k2 = 0; k2 < 32; k2++) hs[k2] = 0.f;

    for (int seg = 0; seg < NSEG; seg++) {
        const size_t base = ((size_t)bh*NSEG + seg)*STATESZ;
        const float E = Esh[seg];
        #pragma unroll
        for (int k2 = 0; k2 < 32; k2++) {
            const size_t e = base + k2*256 + tid;
            g_hstart[e] = hs[k2];
            hs[k2] = fmaf(hs[k2], E, g_states[e]);
        }
    }
}

// =================================================================
// Output scan (pass 3): recurrent, 8-step cp.async staging,
// 2 barriers per 8 steps. grid = BATCH*NHEADS*NSEG, 256 threads.
// smem step layout: [0..63]=x, [64..191]=B, [192..319]=C, [320]=dt, [321]=dA
// =================================================================
#define STEPF 336
__global__ __launch_bounds__(256) void scan_out_kernel(const float* __restrict__ Dvec)
{
    const int blk = blockIdx.x;
    const int bh  = blk >> 4;
    const int seg = blk & (NSEG - 1);
    const int b   = bh / NHEADS, h = bh % NHEADS;
    const int tid = threadIdx.x;
    const int p = tid >> 2, j = tid & 3;
    const int t0 = seg * SEGLEN;
    const size_t rowbase = (size_t)b * LSEQ;

    __shared__ float sh[2][8 * STEPF];

    float hreg[32];
    {
        const size_t base = ((size_t)bh * NSEG + seg) * STATESZ + p * DSTATE + j * 32;
        #pragma unroll
        for (int k = 0; k < 32; k++) hreg[k] = g_hstart[base + k];
    }
    const float Dh = Dvec[h];

    // per-thread cp.async chunk descriptors: e = tid, tid+256, tid+512 (<640)
    // chunk e: tt = e/80, i = e%80; i<16 -> x, else B|C contiguous
    int ctt[3], csc[3], cgc[3];
    #pragma unroll
    for (int q = 0; q < 3; q++) {
        int e = tid + q * 256;
        if (e < 640) {
            int tt = e / 80, i = e % 80;
            ctt[q] = tt;
            csc[q] = (i < 16) ? i * 4 : 64 + (i - 16) * 4;
            cgc[q] = (i < 16) ? (h * HEADDIM + i * 4) : (1536 + (i - 16) * 4);
        } else { ctt[q] = -1; csc[q] = 0; cgc[q] = 0; }
    }

    // issue group g into buffer g&1
    #define ISSUE_GROUP(g)                                                       \
    {                                                                            \
        float* buf = sh[(g) & 1];                                                \
        const size_t r0 = rowbase + t0 + (size_t)(g) * 8;                        \
        _Pragma("unroll")                                                        \
        for (int q = 0; q < 3; q++) {                                            \
            if (ctt[q] >= 0) {                                                   \
                uint32_t d = (uint32_t)__cvta_generic_to_shared(                 \
                    &buf[ctt[q] * STEPF + csc[q]]);                              \
                CPA16(d, g_xBC + (r0 + ctt[q]) * CONVDIM + cgc[q]);              \
            }                                                                    \
        }                                                                        \
        if (tid < 8)                                                             \
            buf[tid * STEPF + 320] = g_dt[(r0 + tid) * NHEADS + h];              \
        else if (tid < 16)                                                       \
            buf[(tid - 8) * STEPF + 321] = g_dA[(r0 + tid - 8) * NHEADS + h];    \
        asm volatile("cp.async.commit_group;\n" ::: "memory");                   \
    }

    ISSUE_GROUP(0);

    for (int g = 0; g < SEGLEN / 8; g++) {
        if (g + 1 < SEGLEN / 8) {
            ISSUE_GROUP(g + 1);
            asm volatile("cp.async.wait_group 1;\n" ::: "memory");
        } else {
            asm volatile("cp.async.wait_group 0;\n" ::: "memory");
        }
        __syncthreads();

        const float* buf = sh[g & 1];
        #pragma unroll
        for (int tt = 0; tt < 8; tt++) {
            const float* sp2 = buf + tt * STEPF;
            const float dtv = sp2[320];
            const float dAv = sp2[321];
            const float xp  = sp2[p];
            const float coef = dtv * xp;
            const float4* B4 = (const float4*)(sp2 + 64  + j*32);
            const float4* C4 = (const float4*)(sp2 + 192 + j*32);
            float acc = 0.f;
            #pragma unroll
            for (int k4 = 0; k4 < 8; k4++) {
                float4 b4 = B4[k4];
                float4 c4 = C4[k4];
                hreg[k4*4+0] = fmaf(hreg[k4*4+0], dAv, coef * b4.x);
                acc = fmaf(hreg[k4*4+0], c4.x, acc);
                hreg[k4*4+1] = fmaf(hreg[k4*4+1], dAv, coef * b4.y);
                acc = fmaf(hreg[k4*4+1], c4.y, acc);
                hreg[k4*4+2] = fmaf(hreg[k4*4+2], dAv, coef * b4.z);
                acc = fmaf(hreg[k4*4+2], c4.z, acc);
                hreg[k4*4+3] = fmaf(hreg[k4*4+3], dAv, coef * b4.w);
                acc = fmaf(hreg[k4*4+3], c4.w, acc);
            }
            acc += __shfl_down_sync(0xffffffffu, acc, 2);
            acc += __shfl_down_sync(0xffffffffu, acc, 1);
            if (j == 0)
                g_y[(rowbase + t0 + g*8 + tt)*DINNER + h*HEADDIM + p] = acc + Dh * xp;
        }
        __syncthreads();   // protect buffer reuse by next ISSUE_GROUP
    }
    #undef ISSUE_GROUP
}

// =================================================================
// y = y * silu(z); y = y * rsqrt(mean(y^2)+eps) * norm_w   (in place)
// =================================================================
__global__ __launch_bounds__(256) void gate_norm_kernel(const float* __restrict__ norm_w)
{
    const int row = blockIdx.x;
    const int tid = threadIdx.x;
    const float* zrow = g_zxbcdt + (size_t)row * DPROJ;
    float* yrow = g_y + (size_t)row * DINNER;

    float v[6];
    float ss = 0.f;
    #pragma unroll
    for (int i = 0; i < 6; i++) {
        int c = tid + i*256;
        float z  = zrow[c];
        float yg = yrow[c] * (z / (1.f + expf(-z)));
        v[i] = yg;
        ss += yg * yg;
    }
    #pragma unroll
    for (int o = 16; o > 0; o >>= 1) ss += __shfl_xor_sync(0xffffffffu, ss, o);
    __shared__ float red[8];
    if ((tid & 31) == 0) red[tid >> 5] = ss;
    __syncthreads();
    if (tid < 32) {
        float s2 = (tid < 8) ? red[tid] : 0.f;
        #pragma unroll
        for (int o = 4; o > 0; o >>= 1) s2 += __shfl_xor_sync(0xffffffffu, s2, o);
        if (tid == 0) red[0] = s2;
    }
    __syncthreads();
    const float rstd = rsqrtf(red[0] * (1.f/1536.f) + 1e-5f);
    #pragma unroll
    for (int i = 0; i < 6; i++) {
        int c = tid + i*256;
        yrow[c] = v[i] * rstd * norm_w[c];
    }
}

// =================================================================
extern "C" void kernel_launch(void* const* d_in, const int* in_sizes, int n_in,
                              void* d_out, int out_size)
{
    const float* feature   = (const float*)d_in[0];
    const float* in_proj_w = (const float*)d_in[1];
    const float* conv_w    = (const float*)d_in[2];
    const float* conv_b    = (const float*)d_in[3];
    const float* dt_bias   = (const float*)d_in[4];
    const float* A_log     = (const float*)d_in[5];
    const float* Dvec      = (const float*)d_in[6];
    const float* norm_w    = (const float*)d_in[7];
    const float* out_projw = (const float*)d_in[8];
    const float* gate1     = (const float*)d_in[9];
    float* out = (float*)d_out;

    float *zx, *y;
    cudaGetSymbolAddress((void**)&zx, g_zxbcdt);
    cudaGetSymbolAddress((void**)&y,  g_y);

    dim3 blk(256);

    gemm_tf32<<<dim3((DPROJ + BN - 1)/BN, ROWS/BM), blk>>>(
        feature, in_proj_w, zx, ROWS, DPROJ, DMODEL, nullptr);

    conv_silu_kernel<<<(int)(((long)ROWS * CONVDIM) / 256), blk>>>(conv_w, conv_b);

    dt_kernel<<<(ROWS * NHEADS) / 256, blk>>>(dt_bias, A_log);

    chunk_state_kernel<<<BATCH * NHEADS * NSEG, blk>>>(A_log);
    combine_kernel<<<BATCH * NHEADS, blk>>>(A_log);
    scan_out_kernel<<<BATCH * NHEADS * NSEG, blk>>>(Dvec);

    gate_norm_kernel<<<ROWS, blk>>>(norm_w);

    gemm_tf32<<<dim3(DMODEL/BN, ROWS/BM), blk>>>(
        y, out_projw, out, ROWS, DMODEL, DINNER, gate1);
}

// round 6
// speedup vs baseline: 3.9396x; 2.8015x over previous
#include <cuda_runtime.h>
#include <math.h>
#include <stdint.h>

#define BATCH   4
#define LSEQ    2048
#define ROWS    (BATCH*LSEQ)      // 8192
#define DMODEL  768
#define DINNER  1536
#define NHEADS  24
#define HEADDIM 64
#define DSTATE  128
#define CONVDIM 1792
#define DPROJ   3352              // 2*DINNER + 2*DSTATE + NHEADS

#define NSEG    16
#define SEGLEN  (LSEQ/NSEG)       // 128
#define STATESZ (HEADDIM*DSTATE)  // 8192

// -------- scratch (device globals; no allocation allowed) --------
__device__ float g_zxbcdt[(size_t)ROWS * DPROJ];   // in_proj output
__device__ float g_xBC[(size_t)ROWS * CONVDIM];    // conv+silu output
__device__ float g_dt[ROWS * NHEADS];
__device__ float g_y[(size_t)ROWS * DINNER];       // scan output -> gated/normed
__device__ float g_states[(size_t)BATCH*NHEADS*NSEG*STATESZ];  // segment end states
__device__ float g_hstart[(size_t)BATCH*NHEADS*NSEG*STATESZ];  // segment start states

// =================================================================
// common PTX helpers
// =================================================================
__device__ __forceinline__ uint32_t f2tf32(float x) {
    uint32_t r;
    asm("cvt.rna.tf32.f32 %0, %1;" : "=r"(r) : "f"(x));
    return r;
}
// split fp32 into tf32 hi + tf32 lo (3xTF32 error compensation)
__device__ __forceinline__ void tsplit(float v, uint32_t& hi, uint32_t& lo) {
    hi = f2tf32(v);
    lo = f2tf32(v - __uint_as_float(hi));
}

#define CPA16(dst, src) \
    asm volatile("cp.async.cg.shared.global [%0], [%1], 16;\n" \
                 :: "r"(dst), "l"(src))
#define CPA16P(dst, src, valid) \
    asm volatile("cp.async.cg.shared.global [%0], [%1], 16, %2;\n" \
                 :: "r"(dst), "l"(src), "r"((valid) ? 16 : 0))
#define CPA_COMMIT() asm volatile("cp.async.commit_group;\n" ::: "memory")
#define CPA_WAIT0()  asm volatile("cp.async.wait_group 0;\n" ::: "memory")

#define MMA_TF32(d, a, b) \
    asm volatile("mma.sync.aligned.m16n8k8.row.col.f32.tf32.tf32.f32 " \
                 "{%0,%1,%2,%3},{%4,%5,%6,%7},{%8,%9},{%0,%1,%2,%3};\n" \
                 : "+f"((d)[0]), "+f"((d)[1]), "+f"((d)[2]), "+f"((d)[3]) \
                 : "r"((a)[0]), "r"((a)[1]), "r"((a)[2]), "r"((a)[3]), \
                   "r"((b)[0]), "r"((b)[1]))

// 3xTF32: d += a*b with error compensation
#define MMA3(d, ah, al, bhv, blv) do { \
    MMA_TF32(d, al, bhv); \
    MMA_TF32(d, ah, blv); \
    MMA_TF32(d, ah, bhv); } while (0)

// =================================================================
// TF32 tensor-core GEMM (NT): C[M,N] = A[M,K] * B[N,K]^T
// =================================================================
#define BM 128
#define BN 128
#define BKT 16

__global__ __launch_bounds__(256) void gemm_tf32(
    const float* __restrict__ A, const float* __restrict__ B,
    float* __restrict__ C, int M, int N, int K,
    const float* __restrict__ gate)
{
    __shared__ float As[2][BM][20];
    __shared__ float Bs[2][BN][20];

    const int tid  = threadIdx.x;
    const int lane = tid & 31;
    const int warp = tid >> 5;
    const int wm   = warp >> 2;
    const int wn   = warp & 3;
    const int m0   = blockIdx.y * BM;
    const int n0   = blockIdx.x * BN;

    const int lr = tid >> 2;
    const int lc = (tid & 3) * 4;

    const float* Ag0 = A + (size_t)(m0 + lr) * K + lc;
    const float* Ag1 = Ag0 + (size_t)64 * K;
    const bool  bv0 = (n0 + lr) < N;
    const bool  bv1 = (n0 + lr + 64) < N;
    const int   br0 = min(n0 + lr, N - 1);
    const int   br1 = min(n0 + lr + 64, N - 1);
    const float* Bg0 = B + (size_t)br0 * K + lc;
    const float* Bg1 = B + (size_t)br1 * K + lc;

    float acc[4][4][4];
    #pragma unroll
    for (int i = 0; i < 4; i++)
        #pragma unroll
        for (int j = 0; j < 4; j++)
            #pragma unroll
            for (int r = 0; r < 4; r++) acc[i][j][r] = 0.f;

    const int KT = K / BKT;

    {
        uint32_t sA0 = (uint32_t)__cvta_generic_to_shared(&As[0][lr][lc]);
        uint32_t sA1 = (uint32_t)__cvta_generic_to_shared(&As[0][lr + 64][lc]);
        uint32_t sB0 = (uint32_t)__cvta_generic_to_shared(&Bs[0][lr][lc]);
        uint32_t sB1 = (uint32_t)__cvta_generic_to_shared(&Bs[0][lr + 64][lc]);
        CPA16(sA0, Ag0);
        CPA16(sA1, Ag1);
        CPA16P(sB0, Bg0, bv0);
        CPA16P(sB1, Bg1, bv1);
        CPA_COMMIT();
    }

    for (int kt = 0; kt < KT; kt++) {
        const int st = kt & 1;
        CPA_WAIT0();
        __syncthreads();

        if (kt + 1 < KT) {
            const int ns = st ^ 1;
            const size_t ko = (size_t)(kt + 1) * BKT;
            uint32_t sA0 = (uint32_t)__cvta_generic_to_shared(&As[ns][lr][lc]);
            uint32_t sA1 = (uint32_t)__cvta_generic_to_shared(&As[ns][lr + 64][lc]);
            uint32_t sB0 = (uint32_t)__cvta_generic_to_shared(&Bs[ns][lr][lc]);
            uint32_t sB1 = (uint32_t)__cvta_generic_to_shared(&Bs[ns][lr + 64][lc]);
            CPA16(sA0, Ag0 + ko);
            CPA16(sA1, Ag1 + ko);
            CPA16P(sB0, Bg0 + ko, bv0);
            CPA16P(sB1, Bg1 + ko, bv1);
            CPA_COMMIT();
        }

        #pragma unroll
        for (int kk = 0; kk < BKT; kk += 8) {
            uint32_t a[4][4], b[4][2];
            const int qr = lane >> 2;
            const int qc = kk + (lane & 3);
            #pragma unroll
            for (int mf = 0; mf < 4; mf++) {
                const int r = wm * 64 + mf * 16 + qr;
                a[mf][0] = f2tf32(As[st][r][qc]);
                a[mf][1] = f2tf32(As[st][r + 8][qc]);
                a[mf][2] = f2tf32(As[st][r][qc + 4]);
                a[mf][3] = f2tf32(As[st][r + 8][qc + 4]);
            }
            #pragma unroll
            for (int nf = 0; nf < 4; nf++) {
                const int r = wn * 32 + nf * 8 + qr;
                b[nf][0] = f2tf32(Bs[st][r][qc]);
                b[nf][1] = f2tf32(Bs[st][r][qc + 4]);
            }
            #pragma unroll
            for (int mf = 0; mf < 4; mf++)
                #pragma unroll
                for (int nf = 0; nf < 4; nf++)
                    MMA_TF32(acc[mf][nf], a[mf], b[nf]);
        }
    }

    float scale = 1.f;
    if (gate) { float g = *gate; scale = 1.f / (1.f + expf(-g)); }

    #pragma unroll
    for (int mf = 0; mf < 4; mf++) {
        const int r = m0 + wm * 64 + mf * 16 + (lane >> 2);
        #pragma unroll
        for (int nf = 0; nf < 4; nf++) {
            const int c = n0 + wn * 32 + nf * 8 + (lane & 3) * 2;
            if (c < N) {
                float2 v0 = make_float2(acc[mf][nf][0] * scale, acc[mf][nf][1] * scale);
                float2 v1 = make_float2(acc[mf][nf][2] * scale, acc[mf][nf][3] * scale);
                *(float2*)&C[(size_t)r * N + c]       = v0;
                *(float2*)&C[(size_t)(r + 8) * N + c] = v1;
            }
        }
    }
}

// =================================================================
// Causal depthwise conv1d (width 4) + bias + SiLU on xBC slice
// =================================================================
__global__ __launch_bounds__(256) void conv_silu_kernel(
    const float* __restrict__ conv_w, const float* __restrict__ conv_b)
{
    const long idx = (long)blockIdx.x * 256 + threadIdx.x;
    const int  c   = (int)(idx % CONVDIM);
    const long row = idx / CONVDIM;
    const int  l   = (int)(row % LSEQ);

    float acc = conv_b[c];
    const float w0 = conv_w[c*4+0], w1 = conv_w[c*4+1];
    const float w2 = conv_w[c*4+2], w3 = conv_w[c*4+3];
    const float* base = g_zxbcdt + (size_t)row * DPROJ + DINNER + c;
    if (l >= 3) acc = fmaf(base[-3*DPROJ], w0, acc);
    if (l >= 2) acc = fmaf(base[-2*DPROJ], w1, acc);
    if (l >= 1) acc = fmaf(base[-1*DPROJ], w2, acc);
    acc = fmaf(base[0], w3, acc);
    g_xBC[idx] = acc / (1.f + expf(-acc));
}

// =================================================================
// dt = softplus(dt_raw + dt_bias)
// =================================================================
__global__ __launch_bounds__(256) void dt_kernel(const float* __restrict__ dt_bias)
{
    const int idx = blockIdx.x * 256 + threadIdx.x;
    const int h   = idx % NHEADS;
    const int row = idx / NHEADS;
    float v  = g_zxbcdt[(size_t)row * DPROJ + (DINNER + CONVDIM) + h] + dt_bias[h];
    float sp = (v > 20.f) ? v : log1pf(expf(v));
    g_dt[idx] = sp;
}

// =================================================================
// K1: fused per-chunk tensor-core kernel (3xTF32).
//   GEMM1: M = C @ B^T  (128x128, K=128), mask -> M~ stored over Csm
//   GEMM2: Y_intra = M~ @ X (+ D*x)  -> g_y
//   GEMM3: S = (w.X)^T @ B           -> g_states
// grid = BATCH*NHEADS*NSEG, 256 threads, ~167KB dynamic smem.
// smem float layout:
//   Csm [128][132] @0      (later M~)
//   Bsm [128][132] @16896
//   xT  [64][132]  @33792  (x transposed: [p][s])
//   sa[128]@42240 sdt[128]@42368 sw[128]@42496 wsum4[4]@42624
// =================================================================
#define K1_SMEM_FLOATS 42628
#define K3_SMEM_FLOATS 25476

__global__ __launch_bounds__(256) void chunk_fused_kernel(
    const float* __restrict__ A_log, const float* __restrict__ Dvec)
{
    extern __shared__ float sm[];
    float* Csm = sm;
    float* Bsm = sm + 16896;
    float* xT  = sm + 33792;
    float* sa  = sm + 42240;
    float* sdt = sm + 42368;
    float* sw  = sm + 42496;
    float* wsum4 = sm + 42624;

    const int blk = blockIdx.x;
    const int bh = blk >> 4, seg = blk & (NSEG - 1);
    const int b = bh / NHEADS, h = bh % NHEADS;
    const int tid = threadIdx.x, lane = tid & 31, warp = tid >> 5;
    const int qr = lane >> 2, ql = lane & 3;
    const size_t rowbase = (size_t)b * LSEQ + seg * SEGLEN;

    // ---- cp.async: B tile [t][n] and C tile [t][n] (128 rows x 32 chunks) ----
    #pragma unroll
    for (int i = 0; i < 16; i++) {
        int e = tid + i * 256;            // < 4096
        int t = e >> 5, ch = (e & 31) * 4;
        const float* srcB = g_xBC + (rowbase + t) * CONVDIM + DINNER + ch;   // B cols
        CPA16((uint32_t)__cvta_generic_to_shared(&Bsm[t*132 + ch]), srcB);
        CPA16((uint32_t)__cvta_generic_to_shared(&Csm[t*132 + ch]), srcB + DSTATE);
    }
    CPA_COMMIT();

    // ---- dt cumsum / weights ----
    const float Aneg = -expf(A_log[h]);
    float vdt = 0.f, acs = 0.f;
    if (tid < SEGLEN) {
        vdt = g_dt[(rowbase + tid) * NHEADS + h];
        acs = vdt;
        #pragma unroll
        for (int o = 1; o < 32; o <<= 1) {
            float nv = __shfl_up_sync(0xffffffffu, acs, o);
            if (lane >= o) acs += nv;
        }
        if (lane == 31) wsum4[warp] = acs;
    }
    __syncthreads();
    if (tid < SEGLEN) {
        float tot = wsum4[0] + wsum4[1] + wsum4[2] + wsum4[3];
        float pre = 0.f;
        #pragma unroll
        for (int w2 = 0; w2 < 4; w2++) if (w2 < warp) pre += wsum4[w2];
        float a = acs + pre;
        sa[tid]  = a;
        sdt[tid] = vdt;
        sw[tid]  = vdt * __expf(Aneg * (tot - a));
    }

    // ---- x load + transpose into xT[p][s] ----
    #pragma unroll
    for (int i = 0; i < 8; i++) {
        int e = tid + i * 256;            // < 2048 (128 s x 16 p-chunks)
        int s = e >> 4, p0 = (e & 15) * 4;
        float4 v = *(const float4*)(g_xBC + (rowbase + s) * CONVDIM + h * HEADDIM + p0);
        xT[(p0+0)*132 + s] = v.x;
        xT[(p0+1)*132 + s] = v.y;
        xT[(p0+2)*132 + s] = v.z;
        xT[(p0+3)*132 + s] = v.w;
    }

    CPA_WAIT0();
    __syncthreads();

    // ================= GEMM1: M = C @ B^T =================
    float mreg[4][4][4];
    #pragma unroll
    for (int i = 0; i < 4; i++)
        #pragma unroll
        for (int j = 0; j < 4; j++)
            #pragma unroll
            for (int r = 0; r < 4; r++) mreg[i][j][r] = 0.f;

    const int m1 = (warp >> 2) * 64, n1 = (warp & 3) * 32;
    #pragma unroll 2
    for (int k = 0; k < 128; k += 8) {
        uint32_t ah[4][4], al[4][4], bh2[4][2], bl2[4][2];
        #pragma unroll
        for (int mf = 0; mf < 4; mf++) {
            int r = m1 + mf*16 + qr;
            tsplit(Csm[r*132 + k + ql],         ah[mf][0], al[mf][0]);
            tsplit(Csm[(r+8)*132 + k + ql],     ah[mf][1], al[mf][1]);
            tsplit(Csm[r*132 + k + 4 + ql],     ah[mf][2], al[mf][2]);
            tsplit(Csm[(r+8)*132 + k + 4 + ql], ah[mf][3], al[mf][3]);
        }
        #pragma unroll
        for (int nf = 0; nf < 4; nf++) {
            int r = n1 + nf*8 + qr;
            tsplit(Bsm[r*132 + k + ql],     bh2[nf][0], bl2[nf][0]);
            tsplit(Bsm[r*132 + k + 4 + ql], bh2[nf][1], bl2[nf][1]);
        }
        #pragma unroll
        for (int mf = 0; mf < 4; mf++)
            #pragma unroll
            for (int nf = 0; nf < 4; nf++)
                MMA3(mreg[mf][nf], ah[mf], al[mf], bh2[nf], bl2[nf]);
    }
    __syncthreads();   // all warps done reading Csm

    // ---- mask + store M~ over Csm ----
    #pragma unroll
    for (int mf = 0; mf < 4; mf++) {
        int tA = m1 + mf*16 + qr, tB = tA + 8;
        float aA = sa[tA], aB = sa[tB];
        #pragma unroll
        for (int nf = 0; nf < 4; nf++) {
            int s0 = n1 + nf*8 + ql*2, s1 = s0 + 1;
            float as0 = sa[s0], as1 = sa[s1];
            float d0 = sdt[s0], d1 = sdt[s1];
            float v00 = (s0 <= tA) ? mreg[mf][nf][0] * __expf(Aneg*(aA-as0)) * d0 : 0.f;
            float v01 = (s1 <= tA) ? mreg[mf][nf][1] * __expf(Aneg*(aA-as1)) * d1 : 0.f;
            float v10 = (s0 <= tB) ? mreg[mf][nf][2] * __expf(Aneg*(aB-as0)) * d0 : 0.f;
            float v11 = (s1 <= tB) ? mreg[mf][nf][3] * __expf(Aneg*(aB-as1)) * d1 : 0.f;
            Csm[tA*132 + s0] = v00;  Csm[tA*132 + s1] = v01;
            Csm[tB*132 + s0] = v10;  Csm[tB*132 + s1] = v11;
        }
    }
    __syncthreads();

    // ================= GEMM2: Y = M~ @ X (B-op = xT[p][s]) =================
    {
        float yreg[2][4][4];
        #pragma unroll
        for (int i = 0; i < 2; i++)
            #pragma unroll
            for (int j = 0; j < 4; j++)
                #pragma unroll
                for (int r = 0; r < 4; r++) yreg[i][j][r] = 0.f;

        const int m2 = (warp >> 1) * 32, n2 = (warp & 1) * 32;
        #pragma unroll 2
        for (int k = 0; k < 128; k += 8) {
            uint32_t ah[2][4], al[2][4], bh2[4][2], bl2[4][2];
            #pragma unroll
            for (int mf = 0; mf < 2; mf++) {
                int r = m2 + mf*16 + qr;
                tsplit(Csm[r*132 + k + ql],         ah[mf][0], al[mf][0]);
                tsplit(Csm[(r+8)*132 + k + ql],     ah[mf][1], al[mf][1]);
                tsplit(Csm[r*132 + k + 4 + ql],     ah[mf][2], al[mf][2]);
                tsplit(Csm[(r+8)*132 + k + 4 + ql], ah[mf][3], al[mf][3]);
            }
            #pragma unroll
            for (int nf = 0; nf < 4; nf++) {
                int r = n2 + nf*8 + qr;
                tsplit(xT[r*132 + k + ql],     bh2[nf][0], bl2[nf][0]);
                tsplit(xT[r*132 + k + 4 + ql], bh2[nf][1], bl2[nf][1]);
            }
            #pragma unroll
            for (int mf = 0; mf < 2; mf++)
                #pragma unroll
                for (int nf = 0; nf < 4; nf++)
                    MMA3(yreg[mf][nf], ah[mf], al[mf], bh2[nf], bl2[nf]);
        }

        const float Dh = Dvec[h];
        #pragma unroll
        for (int mf = 0; mf < 2; mf++) {
            int t = m2 + mf*16 + qr;
            #pragma unroll
            for (int nf = 0; nf < 4; nf++) {
                int p0 = n2 + nf*8 + ql*2;
                float2 o;
                o.x = yreg[mf][nf][0] + Dh * xT[p0*132 + t];
                o.y = yreg[mf][nf][1] + Dh * xT[(p0+1)*132 + t];
                *(float2*)&g_y[(rowbase + t)*DINNER + h*HEADDIM + p0] = o;
                o.x = yreg[mf][nf][2] + Dh * xT[p0*132 + t + 8];
                o.y = yreg[mf][nf][3] + Dh * xT[(p0+1)*132 + t + 8];
                *(float2*)&g_y[(rowbase + t + 8)*DINNER + h*HEADDIM + p0] = o;
            }
        }
    }

    // ================= GEMM3: S = (w.X)^T @ B =================
    {
        float sreg[2][4][4];
        #pragma unroll
        for (int i = 0; i < 2; i++)
            #pragma unroll
            for (int j = 0; j < 4; j++)
                #pragma unroll
                for (int r = 0; r < 4; r++) sreg[i][j][r] = 0.f;

        const int m3 = (warp >> 2) * 32, n3 = (warp & 3) * 32;
        #pragma unroll 2
        for (int k = 0; k < 128; k += 8) {
            float w0 = sw[k + ql], w4 = sw[k + 4 + ql];
            uint32_t ah[2][4], al[2][4], bh2[4][2], bl2[4][2];
            #pragma unroll
            for (int mf = 0; mf < 2; mf++) {
                int r = m3 + mf*16 + qr;
                tsplit(xT[r*132 + k + ql] * w0,         ah[mf][0], al[mf][0]);
                tsplit(xT[(r+8)*132 + k + ql] * w0,     ah[mf][1], al[mf][1]);
                tsplit(xT[r*132 + k + 4 + ql] * w4,     ah[mf][2], al[mf][2]);
                tsplit(xT[(r+8)*132 + k + 4 + ql] * w4, ah[mf][3], al[mf][3]);
            }
            #pragma unroll
            for (int nf = 0; nf < 4; nf++) {
                int n = n3 + nf*8 + qr;
                tsplit(Bsm[(k + ql)*132 + n],     bh2[nf][0], bl2[nf][0]);   // NN-indexed
                tsplit(Bsm[(k + 4 + ql)*132 + n], bh2[nf][1], bl2[nf][1]);
            }
            #pragma unroll
            for (int mf = 0; mf < 2; mf++)
                #pragma unroll
                for (int nf = 0; nf < 4; nf++)
                    MMA3(sreg[mf][nf], ah[mf], al[mf], bh2[nf], bl2[nf]);
        }

        const size_t sbase = ((size_t)bh * NSEG + seg) * STATESZ;
        #pragma unroll
        for (int mf = 0; mf < 2; mf++) {
            int p = m3 + mf*16 + qr;
            #pragma unroll
            for (int nf = 0; nf < 4; nf++) {
                int n0 = n3 + nf*8 + ql*2;
                float2 o0 = make_float2(sreg[mf][nf][0], sreg[mf][nf][1]);
                float2 o1 = make_float2(sreg[mf][nf][2], sreg[mf][nf][3]);
                *(float2*)&g_states[sbase + (size_t)p * DSTATE + n0]       = o0;
                *(float2*)&g_states[sbase + (size_t)(p + 8) * DSTATE + n0] = o1;
            }
        }
    }
}

// =================================================================
// K2: combine: h_start[seg+1] = E_seg * h_start[seg] + S_seg
// =================================================================
__global__ __launch_bounds__(256) void combine_kernel(const float* __restrict__ A_log)
{
    const int bh = blockIdx.x;
    const int b = bh / NHEADS, h = bh % NHEADS;
    const int tid = threadIdx.x;

    __shared__ float part[256];
    __shared__ float Esh[NSEG];

    {
        const int k = tid >> 4, i = tid & 15;
        float s = 0.f;
        const size_t base = ((size_t)b*LSEQ + k*SEGLEN + i*8)*NHEADS + h;
        #pragma unroll
        for (int t = 0; t < 8; t++) s += g_dt[base + (size_t)t*NHEADS];
        part[tid] = s;
    }
    __syncthreads();
    if (tid < NSEG) {
        float s = 0.f;
        #pragma unroll
        for (int i = 0; i < 16; i++) s += part[tid*16 + i];
        Esh[tid] = expf(-expf(A_log[h]) * s);
    }
    __syncthreads();

    float hs[32];
    #pragma unroll
    for (int k2 = 0; k2 < 32; k2++) hs[k2] = 0.f;

    for (int seg = 0; seg < NSEG; seg++) {
        const size_t base = ((size_t)bh*NSEG + seg)*STATESZ;
        const float E = Esh[seg];
        #pragma unroll
        for (int k2 = 0; k2 < 32; k2++) {
            const size_t e = base + k2*256 + tid;
            g_hstart[e] = hs[k2];
            hs[k2] = fmaf(hs[k2], E, g_states[e]);
        }
    }
}

// =================================================================
// K3: inter-chunk: Y += exp(A*a_t) * (C @ hstart^T)   (3xTF32)
// smem: Csm[128][132]@0, Hsm[64][132]@16896, su[128]@25344, wsum4@25472
// =================================================================
__global__ __launch_bounds__(256) void inter_kernel(const float* __restrict__ A_log)
{
    extern __shared__ float sm[];
    float* Csm = sm;
    float* Hsm = sm + 16896;
    float* su  = sm + 25344;
    float* wsum4 = sm + 25472;

    const int blk = blockIdx.x;
    const int bh = blk >> 4, seg = blk & (NSEG - 1);
    const int b = bh / NHEADS, h = bh % NHEADS;
    const int tid = threadIdx.x, lane = tid & 31, warp = tid >> 5;
    const int qr = lane >> 2, ql = lane & 3;
    const size_t rowbase = (size_t)b * LSEQ + seg * SEGLEN;
    const size_t hbase = ((size_t)bh * NSEG + seg) * STATESZ;

    // C tile: 128 rows x 32 chunks
    #pragma unroll
    for (int i = 0; i < 16; i++) {
        int e = tid + i * 256;            // < 4096
        int t = e >> 5, ch = (e & 31) * 4;
        const float* srcC = g_xBC + (rowbase + t) * CONVDIM + DINNER + DSTATE + ch;
        CPA16((uint32_t)__cvta_generic_to_shared(&Csm[t*132 + ch]), srcC);
    }
    // H tile: 64 rows x 32 chunks
    #pragma unroll
    for (int i = 0; i < 8; i++) {
        int e = tid + i * 256;            // < 2048
        int p = e >> 5, ch = (e & 31) * 4;
        const float* srcH = g_hstart + hbase + (size_t)p * DSTATE + ch;
        CPA16((uint32_t)__cvta_generic_to_shared(&Hsm[p*132 + ch]), srcH);
    }
    CPA_COMMIT();

    // cumsum -> u_t = exp(A * a_t)
    const float Aneg = -expf(A_log[h]);
    float vdt = 0.f, acs = 0.f;
    if (tid < SEGLEN) {
        vdt = g_dt[(rowbase + tid) * NHEADS + h];
        acs = vdt;
        #pragma unroll
        for (int o = 1; o < 32; o <<= 1) {
            float nv = __shfl_up_sync(0xffffffffu, acs, o);
            if (lane >= o) acs += nv;
        }
        if (lane == 31) wsum4[warp] = acs;
    }
    __syncthreads();
    if (tid < SEGLEN) {
        float pre = 0.f;
        #pragma unroll
        for (int w2 = 0; w2 < 4; w2++) if (w2 < warp) pre += wsum4[w2];
        su[tid] = __expf(Aneg * (acs + pre));
    }

    CPA_WAIT0();
    __syncthreads();

    float yreg[2][4][4];
    #pragma unroll
    for (int i = 0; i < 2; i++)
        #pragma unroll
        for (int j = 0; j < 4; j++)
            #pragma unroll
            for (int r = 0; r < 4; r++) yreg[i][j][r] = 0.f;

    const int m2 = (warp >> 1) * 32, n2 = (warp & 1) * 32;
    #pragma unroll 2
    for (int k = 0; k < 128; k += 8) {
        uint32_t ah[2][4], al[2][4], bh2[4][2], bl2[4][2];
        #pragma unroll
        for (int mf = 0; mf < 2; mf++) {
            int r = m2 + mf*16 + qr;
            tsplit(Csm[r*132 + k + ql],         ah[mf][0], al[mf][0]);
            tsplit(Csm[(r+8)*132 + k + ql],     ah[mf][1], al[mf][1]);
            tsplit(Csm[r*132 + k + 4 + ql],     ah[mf][2], al[mf][2]);
            tsplit(Csm[(r+8)*132 + k + 4 + ql], ah[mf][3], al[mf][3]);
        }
        #pragma unroll
        for (int nf = 0; nf < 4; nf++) {
            int r = n2 + nf*8 + qr;
            tsplit(Hsm[r*132 + k + ql],     bh2[nf][0], bl2[nf][0]);
            tsplit(Hsm[r*132 + k + 4 + ql], bh2[nf][1], bl2[nf][1]);
        }
        #pragma unroll
        for (int mf = 0; mf < 2; mf++)
            #pragma unroll
            for (int nf = 0; nf < 4; nf++)
                MMA3(yreg[mf][nf], ah[mf], al[mf], bh2[nf], bl2[nf]);
    }

    #pragma unroll
    for (int mf = 0; mf < 2; mf++) {
        int t = m2 + mf*16 + qr;
        float u0 = su[t], u1 = su[t + 8];
        #pragma unroll
        for (int nf = 0; nf < 4; nf++) {
            int p0 = n2 + nf*8 + ql*2;
            float* addr0 = &g_y[(rowbase + t)*DINNER + h*HEADDIM + p0];
            float* addr1 = &g_y[(rowbase + t + 8)*DINNER + h*HEADDIM + p0];
            float2 o0 = *(float2*)addr0;
            float2 o1 = *(float2*)addr1;
            o0.x += u0 * yreg[mf][nf][0];  o0.y += u0 * yreg[mf][nf][1];
            o1.x += u1 * yreg[mf][nf][2];  o1.y += u1 * yreg[mf][nf][3];
            *(float2*)addr0 = o0;
            *(float2*)addr1 = o1;
        }
    }
}

// =================================================================
// y = y * silu(z); y = y * rsqrt(mean(y^2)+eps) * norm_w   (in place)
// =================================================================
__global__ __launch_bounds__(256) void gate_norm_kernel(const float* __restrict__ norm_w)
{
    const int row = blockIdx.x;
    const int tid = threadIdx.x;
    const float* zrow = g_zxbcdt + (size_t)row * DPROJ;
    float* yrow = g_y + (size_t)row * DINNER;

    float v[6];
    float ss = 0.f;
    #pragma unroll
    for (int i = 0; i < 6; i++) {
        int c = tid + i*256;
        float z  = zrow[c];
        float yg = yrow[c] * (z / (1.f + expf(-z)));
        v[i] = yg;
        ss += yg * yg;
    }
    #pragma unroll
    for (int o = 16; o > 0; o >>= 1) ss += __shfl_xor_sync(0xffffffffu, ss, o);
    __shared__ float red[8];
    if ((tid & 31) == 0) red[tid >> 5] = ss;
    __syncthreads();
    if (tid < 32) {
        float s2 = (tid < 8) ? red[tid] : 0.f;
        #pragma unroll
        for (int o = 4; o > 0; o >>= 1) s2 += __shfl_xor_sync(0xffffffffu, s2, o);
        if (tid == 0) red[0] = s2;
    }
    __syncthreads();
    const float rstd = rsqrtf(red[0] * (1.f/1536.f) + 1e-5f);
    #pragma unroll
    for (int i = 0; i < 6; i++) {
        int c = tid + i*256;
        yrow[c] = v[i] * rstd * norm_w[c];
    }
}

// =================================================================
extern "C" void kernel_launch(void* const* d_in, const int* in_sizes, int n_in,
                              void* d_out, int out_size)
{
    const float* feature   = (const float*)d_in[0];
    const float* in_proj_w = (const float*)d_in[1];
    const float* conv_w    = (const float*)d_in[2];
    const float* conv_b    = (const float*)d_in[3];
    const float* dt_bias   = (const float*)d_in[4];
    const float* A_log     = (const float*)d_in[5];
    const float* Dvec      = (const float*)d_in[6];
    const float* norm_w    = (const float*)d_in[7];
    const float* out_projw = (const float*)d_in[8];
    const float* gate1     = (const float*)d_in[9];
    float* out = (float*)d_out;

    float *zx, *y;
    cudaGetSymbolAddress((void**)&zx, g_zxbcdt);
    cudaGetSymbolAddress((void**)&y,  g_y);

    cudaFuncSetAttribute(chunk_fused_kernel,
        cudaFuncAttributeMaxDynamicSharedMemorySize, K1_SMEM_FLOATS * 4);
    cudaFuncSetAttribute(inter_kernel,
        cudaFuncAttributeMaxDynamicSharedMemorySize, K3_SMEM_FLOATS * 4);

    dim3 blk(256);

    gemm_tf32<<<dim3((DPROJ + BN - 1)/BN, ROWS/BM), blk>>>(
        feature, in_proj_w, zx, ROWS, DPROJ, DMODEL, nullptr);

    conv_silu_kernel<<<(int)(((long)ROWS * CONVDIM) / 256), blk>>>(conv_w, conv_b);

    dt_kernel<<<(ROWS * NHEADS) / 256, blk>>>(dt_bias);

    chunk_fused_kernel<<<BATCH * NHEADS * NSEG, blk, K1_SMEM_FLOATS * 4>>>(A_log, Dvec);
    combine_kernel<<<BATCH * NHEADS, blk>>>(A_log);
    inter_kernel<<<BATCH * NHEADS * NSEG, blk, K3_SMEM_FLOATS * 4>>>(A_log);

    gate_norm_kernel<<<ROWS, blk>>>(norm_w);

    gemm_tf32<<<dim3(DMODEL/BN, ROWS/BM), blk>>>(
        y, out_projw, out, ROWS, DMODEL, DINNER, gate1);
}